// round 12
// baseline (speedup 1.0000x reference)
#include <cuda_runtime.h>
#include <math.h>

#define NB 64
#define MM 64
#define NN 128
#define KIT 10

// ---------------- persistent device state ----------------------------------
__device__ double2 g_Theta[NB * NN * NN];
__device__ double2 g_Lamda[NB * NN * NN];
__device__ double2 g_A[NB * NN * NN];
__device__ double2 g_V[NB * NN * NN];
__device__ double2 g_S[NB * NN * NN];
__device__ double2 g_T[NB * MM * MM];
__device__ double  g_minv[KIT * NB * NN];
__device__ double  g_sd[NB * NN];

// ---------------- threefry2x32 (JAX-compatible) ----------------------------
__device__ __forceinline__ void tf2x32(unsigned k0, unsigned k1,
                                       unsigned &x0, unsigned &x1) {
    unsigned ks2 = k0 ^ k1 ^ 0x1BD11BDAu;
    x0 += k0; x1 += k1;
#define TF_ROT(x, d) (((x) << (d)) | ((x) >> (32 - (d))))
#define TF_RND(r) do { x0 += x1; x1 = TF_ROT(x1, r); x1 ^= x0; } while (0)
    TF_RND(13); TF_RND(15); TF_RND(26); TF_RND(6);
    x0 += k1;  x1 += ks2 + 1u;
    TF_RND(17); TF_RND(29); TF_RND(16); TF_RND(24);
    x0 += ks2; x1 += k0 + 2u;
    TF_RND(13); TF_RND(15); TF_RND(26); TF_RND(6);
    x0 += k0;  x1 += k1 + 3u;
    TF_RND(17); TF_RND(29); TF_RND(16); TF_RND(24);
    x0 += k1;  x1 += ks2 + 4u;
    TF_RND(13); TF_RND(15); TF_RND(26); TF_RND(6);
    x0 += ks2; x1 += k0 + 5u;
#undef TF_RND
#undef TF_ROT
}

// minv[it][b][j] = sqrt(2)*erfinv(uniform(lo=nextafter(-1,0), hi=1))
// partitionable threefry: counter = (0, flat_index), bits = y0<<32 | y1.
__global__ void minv_kernel() {
    int idx = blockIdx.x * blockDim.x + threadIdx.x;
    if (idx >= KIT * NB * NN) return;
    int it = idx / (NB * NN);
    unsigned i = (unsigned)(idx % (NB * NN));

    unsigned k0 = 0u, k1 = (unsigned)it;     // fold_in(key(42), it)
    tf2x32(0u, 42u, k0, k1);

    unsigned y0 = 0u, y1 = i;
    tf2x32(k0, k1, y0, y1);
    unsigned long long bits = ((unsigned long long)y0 << 32) | (unsigned long long)y1;
    unsigned long long fb = (bits >> 12) | 0x3FF0000000000000ULL;
    double f  = __longlong_as_double((long long)fb) - 1.0;
    double lo = __longlong_as_double((long long)0xBFEFFFFFFFFFFFFFULL);
    double u  = f * 2.0 + lo;
    u = fmax(lo, u);
    g_minv[idx] = 1.4142135623730951 * erfinv(u);
}

__global__ void zero_kernel() {
    int idx = blockIdx.x * blockDim.x + threadIdx.x;
    if (idx < NB * NN * NN) {
        g_Theta[idx] = make_double2(0.0, 0.0);
        g_Lamda[idx] = make_double2(0.0, 0.0);
    }
}

// --------- per-iteration: StackM (g_S), T block, A = StackM - Lamda/r -------
__global__ void prepare_kernel(const float* __restrict__ Yr,
                               const float* __restrict__ Yi,
                               const float* __restrict__ rho,
                               const float* __restrict__ tau, int it) {
    int b = blockIdx.x;
    int tid = threadIdx.x;              // 256
    double r = (double)rho[it];
    double t = (double)tau[it];
    size_t base = (size_t)b * NN * NN;

    __shared__ double2 su[MM];
    if (tid < MM) {
        int k = tid;
        double ax = 0.0, ay = 0.0;
        for (int i = 0; i + k < MM; ++i) {
            double2 L  = g_Lamda[base + (size_t)i * NN + i + k];
            double2 Th = g_Theta[base + (size_t)i * NN + i + k];
            ax += L.x + r * Th.x;
            ay += L.y + r * Th.y;
        }
        if (k == 0) ax += -(t * 0.5) * (double)MM;
        double sc = (1.0 / (double)(MM - k)) / r;
        su[k] = make_double2(ax * sc, ay * sc);
    }
    __syncthreads();

    double inv1 = 1.0 / (1.0 + 2.0 * r);
    double invr = 1.0 / r;
    double tdr  = t / (2.0 * r);
    for (int idx = tid; idx < NN * NN; idx += blockDim.x) {
        int i = idx >> 7, j = idx & 127;
        double2 S;
        if (i < MM && j < MM) {
            S = (j >= i) ? su[j - i] : make_double2(su[i - j].x, -su[i - j].y);
            g_T[(size_t)b * MM * MM + i * MM + j] = S;
        } else if (i < MM) {                       // X block
            int jj = j - MM;
            double2 L = g_Lamda[base + idx], Th = g_Theta[base + idx];
            double yr = (double)Yr[(size_t)b * MM * MM + i * MM + jj];
            double yi = (double)Yi[(size_t)b * MM * MM + i * MM + jj];
            S.x = (yr + 2.0 * L.x + 2.0 * r * Th.x) * inv1;
            S.y = (yi + 2.0 * L.y + 2.0 * r * Th.y) * inv1;
        } else if (j < MM) {                       // conj(X[j][i-MM])
            int ii = j, jj = i - MM;
            size_t xo = base + (size_t)ii * NN + MM + jj;
            double2 L = g_Lamda[xo], Th = g_Theta[xo];
            double yr = (double)Yr[(size_t)b * MM * MM + ii * MM + jj];
            double yi = (double)Yi[(size_t)b * MM * MM + ii * MM + jj];
            S.x =  (yr + 2.0 * L.x + 2.0 * r * Th.x) * inv1;
            S.y = -((yi + 2.0 * L.y + 2.0 * r * Th.y) * inv1);
        } else {                                   // W block
            double2 L = g_Lamda[base + idx], Th = g_Theta[base + idx];
            S.x = L.x * invr + Th.x - ((i == j) ? tdr : 0.0);
            S.y = L.y * invr + Th.y;
        }
        g_S[base + idx] = S;
        double2 L = g_Lamda[base + idx];
        g_A[base + idx] = make_double2(S.x - L.x * invr, S.y - L.y * invr);
    }
}

// ---------------- parallel complex Hermitian Jacobi -------------------------
__global__ __launch_bounds__(512, 1) void jacobi_kernel() {
    int b = blockIdx.x, tid = threadIdx.x;
    double2* __restrict__ A = g_A + (size_t)b * NN * NN;
    double2* __restrict__ V = g_V + (size_t)b * NN * NN;

    __shared__ int    sp[64], sq[64];
    __shared__ double scc[64], ssr[64], ssi[64];
    __shared__ double red[512];
    __shared__ double s_tol2, s_off2;

    for (int idx = tid; idx < NN * NN; idx += 512) {
        int i = idx >> 7, j = idx & 127;
        V[idx] = make_double2(i == j ? 1.0 : 0.0, 0.0);
    }
    double acc = 0.0;
    for (int idx = tid; idx < NN * NN; idx += 512) {
        double2 a = A[idx]; acc += a.x * a.x + a.y * a.y;
    }
    red[tid] = acc; __syncthreads();
    for (int s = 256; s > 0; s >>= 1) { if (tid < s) red[tid] += red[tid + s]; __syncthreads(); }
    if (tid == 0) s_tol2 = red[0] * 1e-26;
    __syncthreads();

    for (int sweep = 0; sweep < 16; ++sweep) {
        acc = 0.0;
        for (int idx = tid; idx < NN * NN; idx += 512) {
            int i = idx >> 7, j = idx & 127;
            if (i != j) { double2 a = A[idx]; acc += a.x * a.x + a.y * a.y; }
        }
        red[tid] = acc; __syncthreads();
        for (int s = 256; s > 0; s >>= 1) { if (tid < s) red[tid] += red[tid + s]; __syncthreads(); }
        if (tid == 0) s_off2 = red[0];
        __syncthreads();
        if (s_off2 <= s_tol2) break;

        for (int r = 0; r < NN - 1; ++r) {
            if (tid < 64) {
                int p, q;
                if (tid == 0) { p = NN - 1; q = r % (NN - 1); }
                else {
                    p = (r + tid) % (NN - 1);
                    q = (r - tid + 2 * (NN - 1)) % (NN - 1);
                }
                sp[tid] = p; sq[tid] = q;
                double app = A[(size_t)p * NN + p].x;
                double aqq = A[(size_t)q * NN + q].x;
                double2 apq = A[(size_t)p * NN + q];
                double mag2 = apq.x * apq.x + apq.y * apq.y;
                double c = 1.0, zr = 0.0, zi = 0.0;
                if (mag2 > 1e-300) {
                    double mag = sqrt(mag2);
                    double th  = (aqq - app) / (2.0 * mag);
                    double rt  = sqrt(th * th + 1.0);
                    double tt  = (th >= 0.0) ? 1.0 / (th + rt) : -1.0 / (rt - th);
                    c = 1.0 / sqrt(1.0 + tt * tt);
                    double sg = tt * c / mag;
                    zr = sg * apq.x; zi = sg * apq.y;
                }
                scc[tid] = c; ssr[tid] = zr; ssi[tid] = zi;
            }
            __syncthreads();
            // phase 2: B = R^H A (row mixing, coalesced)
            for (int item = tid; item < 64 * NN; item += 512) {
                int m = item >> 7, j = item & 127;
                int p = sp[m], q = sq[m];
                double c = scc[m], zr = ssr[m], zi = ssi[m];
                double2 ap = A[(size_t)p * NN + j];
                double2 aq = A[(size_t)q * NN + j];
                double2 np, nq;
                np.x = c * ap.x - (zr * aq.x - zi * aq.y);
                np.y = c * ap.y - (zr * aq.y + zi * aq.x);
                nq.x = (zr * ap.x + zi * ap.y) + c * aq.x;
                nq.y = (zr * ap.y - zi * ap.x) + c * aq.y;
                A[(size_t)p * NN + j] = np;
                A[(size_t)q * NN + j] = nq;
            }
            __syncthreads();
            // phase 3: A = B R, V = V R (per-row column mixing)
            for (int item = tid; item < 64 * NN; item += 512) {
                int i = item >> 6, m = item & 63;
                int p = sp[m], q = sq[m];
                double c = scc[m], zr = ssr[m], zi = ssi[m];
                size_t ro = (size_t)i * NN;
                double2 bp = A[ro + p], bq = A[ro + q];
                double2 np, nq;
                np.x = c * bp.x - (zr * bq.x + zi * bq.y);
                np.y = c * bp.y - (zr * bq.y - zi * bq.x);
                nq.x = (zr * bp.x - zi * bp.y) + c * bq.x;
                nq.y = (zr * bp.y + zi * bp.x) + c * bq.y;
                A[ro + p] = np; A[ro + q] = nq;
                double2 vp = V[ro + p], vq = V[ro + q];
                np.x = c * vp.x - (zr * vq.x + zi * vq.y);
                np.y = c * vp.y - (zr * vq.y - zi * vq.x);
                nq.x = (zr * vp.x - zi * vp.y) + c * vq.x;
                nq.y = (zr * vp.y + zi * vp.x) + c * vq.y;
                V[ro + p] = np; V[ro + q] = nq;
            }
            __syncthreads();
        }
    }
}

// ------- rank eigenvalues ascending, shift by minv[rank], clip at 0 ---------
__global__ void rank_clip_kernel(int it) {
    int b = blockIdx.x, j = threadIdx.x;   // 128 threads
    __shared__ double w[NN];
    w[j] = g_A[(size_t)b * NN * NN + (size_t)j * NN + j].x;
    __syncthreads();
    double wj = w[j];
    int rank = 0;
    for (int k = 0; k < NN; ++k) {
        double wk = w[k];
        rank += (wk < wj) || (wk == wj && k < j);
    }
    double d = wj + g_minv[((size_t)it * NB + b) * NN + rank];
    g_sd[b * NN + j] = d > 0.0 ? d : 0.0;
}

// ---- Sita = V diag(d) V^H ; Theta = Sita ; Lamda += e*(Sita - StackM) ------
__global__ __launch_bounds__(256) void sita_update_kernel(const float* __restrict__ eta, int it) {
    int bid = blockIdx.x;
    int b  = bid >> 4;
    int ti = (bid >> 2) & 3, tj = bid & 3;
    double e = (double)eta[it];
    size_t base = (size_t)b * NN * NN;
    const double2* __restrict__ V = g_V + base;

    __shared__ double2 As[32][33];
    __shared__ double2 Bs[32][33];
    int tx = threadIdx.x & 15, ty = threadIdx.x >> 4;
    int i0 = ti * 32, j0 = tj * 32;
    double2 acc[2][2];
    acc[0][0] = acc[0][1] = acc[1][0] = acc[1][1] = make_double2(0.0, 0.0);

    for (int k0 = 0; k0 < NN; k0 += 32) {
        for (int l = threadIdx.x; l < 32 * 32; l += 256) {
            int rr = l >> 5, kk = l & 31;
            double dk = g_sd[b * NN + k0 + kk];
            double2 v = V[(size_t)(i0 + rr) * NN + k0 + kk];
            As[rr][kk] = make_double2(v.x * dk, v.y * dk);
            Bs[rr][kk] = V[(size_t)(j0 + rr) * NN + k0 + kk];
        }
        __syncthreads();
#pragma unroll 8
        for (int kk = 0; kk < 32; ++kk) {
            double2 a0 = As[ty][kk],      a1 = As[ty + 16][kk];
            double2 b0 = Bs[tx][kk],      b1 = Bs[tx + 16][kk];
            acc[0][0].x += a0.x * b0.x + a0.y * b0.y; acc[0][0].y += a0.y * b0.x - a0.x * b0.y;
            acc[0][1].x += a0.x * b1.x + a0.y * b1.y; acc[0][1].y += a0.y * b1.x - a0.x * b1.y;
            acc[1][0].x += a1.x * b0.x + a1.y * b0.y; acc[1][0].y += a1.y * b0.x - a1.x * b0.y;
            acc[1][1].x += a1.x * b1.x + a1.y * b1.y; acc[1][1].y += a1.y * b1.x - a1.x * b1.y;
        }
        __syncthreads();
    }
    for (int r2 = 0; r2 < 2; ++r2)
        for (int c2 = 0; c2 < 2; ++c2) {
            int gi = i0 + ty + 16 * r2, gj = j0 + tx + 16 * c2;
            size_t idx = base + (size_t)gi * NN + gj;
            double2 s = acc[r2][c2];
            g_Theta[idx] = s;
            double2 L = g_Lamda[idx];
            double2 S = g_S[idx];
            L.x += e * (s.x - S.x);
            L.y += e * (s.y - S.y);
            g_Lamda[idx] = L;
        }
}

// ---------------- output writers (dtype-adaptive, never exceed out_size) ----
// Interleaved float32 (re, im): layout [T (b,i,j) pairs..., uvec (b,k) pairs...]
__global__ void output_f32i_kernel(float* __restrict__ out, int out_elems) {
    int b = blockIdx.x, tid = threadIdx.x;   // 256
    const double2* T = g_T + (size_t)b * MM * MM;
    for (int idx = tid; idx < MM * MM; idx += 256) {
        double2 v = T[idx];
        size_t o = ((size_t)b * MM * MM + idx) * 2;
        if (o + 1 < (size_t)out_elems) {
            out[o]     = (float)v.x;
            out[o + 1] = (float)v.y;
        }
    }
    if (tid < MM) {
        int k = tid;
        double ax = 0.0, ay = 0.0;
        for (int i = k; i < MM; ++i) {
            double2 v = T[(size_t)i * MM + (i - k)];
            ax += v.x; ay += v.y;
        }
        double nk = 1.0 / (double)(MM - k);
        size_t o = 2 * (size_t)NB * MM * MM + ((size_t)b * MM + k) * 2;
        if (o + 1 < (size_t)out_elems) {
            out[o]     = (float)(ax * nk);
            out[o + 1] = (float)(ay * nk);
        }
    }
}

// Real-only float32: layout [T.real flat..., uvec.real flat...]
__global__ void output_f32r_kernel(float* __restrict__ out, int out_elems) {
    int b = blockIdx.x, tid = threadIdx.x;   // 256
    const double2* T = g_T + (size_t)b * MM * MM;
    for (int idx = tid; idx < MM * MM; idx += 256) {
        size_t o = (size_t)b * MM * MM + idx;
        if (o < (size_t)out_elems) out[o] = (float)T[idx].x;
    }
    if (tid < MM) {
        int k = tid;
        double ax = 0.0;
        for (int i = k; i < MM; ++i) ax += T[(size_t)i * MM + (i - k)].x;
        size_t o = (size_t)NB * MM * MM + (size_t)b * MM + k;
        if (o < (size_t)out_elems) out[o] = (float)(ax / (double)(MM - k));
    }
}

extern "C" void kernel_launch(void* const* d_in, const int* in_sizes, int n_in,
                              void* d_out, int out_size) {
    const float* Yr  = (const float*)d_in[0];
    const float* Yi  = (const float*)d_in[1];
    const float* rho = (const float*)d_in[2];
    const float* tau = (const float*)d_in[3];
    const float* eta = (const float*)d_in[4];

    zero_kernel<<<(NB * NN * NN + 255) / 256, 256>>>();
    minv_kernel<<<(KIT * NB * NN + 255) / 256, 256>>>();

    for (int it = 0; it < KIT; ++it) {
        prepare_kernel<<<NB, 256>>>(Yr, Yi, rho, tau, it);
        jacobi_kernel<<<NB, 512>>>();
        rank_clip_kernel<<<NB, NN>>>(it);
        sita_update_kernel<<<NB * 16, 256>>>(eta, it);
    }

    const long long total_c = (long long)NB * MM * MM + (long long)NB * MM; // 266240
    if ((long long)out_size >= 2 * total_c) {
        output_f32i_kernel<<<NB, 256>>>((float*)d_out, out_size);
    } else {
        output_f32r_kernel<<<NB, 256>>>((float*)d_out, out_size);
    }
}

// round 13
// speedup vs baseline: 17.0175x; 17.0175x over previous
#include <cuda_runtime.h>
#include <math.h>

#define NB 64
#define MM 64
#define NN 128
#define KIT 10
#define SROW 129   // padded smem row stride (float2)

// ---------------- persistent device state ----------------------------------
__device__ double2 g_Theta[NB * NN * NN];   // fp64 ADMM state
__device__ double2 g_Lamda[NB * NN * NN];
__device__ double2 g_S[NB * NN * NN];       // StackM (fp64)
__device__ double2 g_T[NB * MM * MM];
__device__ float2  g_Af[NB * NN * NN];      // fp32 eig input
__device__ float2  g_Vf[NB * NN * NN];      // fp32 eigenvectors, stored TRANSPOSED: VT[k][i] = V[i][k]
__device__ double  g_minv[KIT * NB * NN];
__device__ double  g_w[NB * NN];            // eigenvalues (fp64 from fp32 diag)
__device__ float   g_sdf[NB * NN];          // shifted+clipped eigenvalues (fp32)

// ---------------- threefry2x32 (JAX-compatible) ----------------------------
__device__ __forceinline__ void tf2x32(unsigned k0, unsigned k1,
                                       unsigned &x0, unsigned &x1) {
    unsigned ks2 = k0 ^ k1 ^ 0x1BD11BDAu;
    x0 += k0; x1 += k1;
#define TF_ROT(x, d) (((x) << (d)) | ((x) >> (32 - (d))))
#define TF_RND(r) do { x0 += x1; x1 = TF_ROT(x1, r); x1 ^= x0; } while (0)
    TF_RND(13); TF_RND(15); TF_RND(26); TF_RND(6);
    x0 += k1;  x1 += ks2 + 1u;
    TF_RND(17); TF_RND(29); TF_RND(16); TF_RND(24);
    x0 += ks2; x1 += k0 + 2u;
    TF_RND(13); TF_RND(15); TF_RND(26); TF_RND(6);
    x0 += k0;  x1 += k1 + 3u;
    TF_RND(17); TF_RND(29); TF_RND(16); TF_RND(24);
    x0 += k1;  x1 += ks2 + 4u;
    TF_RND(13); TF_RND(15); TF_RND(26); TF_RND(6);
    x0 += ks2; x1 += k0 + 5u;
#undef TF_RND
#undef TF_ROT
}

__global__ void minv_kernel() {
    int idx = blockIdx.x * blockDim.x + threadIdx.x;
    if (idx >= KIT * NB * NN) return;
    int it = idx / (NB * NN);
    unsigned i = (unsigned)(idx % (NB * NN));
    unsigned k0 = 0u, k1 = (unsigned)it;
    tf2x32(0u, 42u, k0, k1);
    unsigned y0 = 0u, y1 = i;
    tf2x32(k0, k1, y0, y1);
    unsigned long long bits = ((unsigned long long)y0 << 32) | (unsigned long long)y1;
    unsigned long long fb = (bits >> 12) | 0x3FF0000000000000ULL;
    double f  = __longlong_as_double((long long)fb) - 1.0;
    double lo = __longlong_as_double((long long)0xBFEFFFFFFFFFFFFFULL);
    double u  = f * 2.0 + lo;
    u = fmax(lo, u);
    g_minv[idx] = 1.4142135623730951 * erfinv(u);
}

__global__ void zero_kernel() {
    int idx = blockIdx.x * blockDim.x + threadIdx.x;
    if (idx < NB * NN * NN) {
        g_Theta[idx] = make_double2(0.0, 0.0);
        g_Lamda[idx] = make_double2(0.0, 0.0);
    }
}

// --------- per-iteration: StackM (g_S), T block, A_f32 = StackM - Lamda/r ---
__global__ void prepare_kernel(const float* __restrict__ Yr,
                               const float* __restrict__ Yi,
                               const float* __restrict__ rho,
                               const float* __restrict__ tau, int it) {
    int b = blockIdx.x;
    int tid = threadIdx.x;              // 256
    double r = (double)rho[it];
    double t = (double)tau[it];
    size_t base = (size_t)b * NN * NN;

    __shared__ double2 su[MM];
    if (tid < MM) {
        int k = tid;
        double ax = 0.0, ay = 0.0;
        for (int i = 0; i + k < MM; ++i) {
            double2 L  = g_Lamda[base + (size_t)i * NN + i + k];
            double2 Th = g_Theta[base + (size_t)i * NN + i + k];
            ax += L.x + r * Th.x;
            ay += L.y + r * Th.y;
        }
        if (k == 0) ax += -(t * 0.5) * (double)MM;
        double sc = (1.0 / (double)(MM - k)) / r;
        su[k] = make_double2(ax * sc, ay * sc);
    }
    __syncthreads();

    double inv1 = 1.0 / (1.0 + 2.0 * r);
    double invr = 1.0 / r;
    double tdr  = t / (2.0 * r);
    for (int idx = tid; idx < NN * NN; idx += blockDim.x) {
        int i = idx >> 7, j = idx & 127;
        double2 S;
        if (i < MM && j < MM) {
            S = (j >= i) ? su[j - i] : make_double2(su[i - j].x, -su[i - j].y);
            g_T[(size_t)b * MM * MM + i * MM + j] = S;
        } else if (i < MM) {
            int jj = j - MM;
            double2 L = g_Lamda[base + idx], Th = g_Theta[base + idx];
            double yr = (double)Yr[(size_t)b * MM * MM + i * MM + jj];
            double yi = (double)Yi[(size_t)b * MM * MM + i * MM + jj];
            S.x = (yr + 2.0 * L.x + 2.0 * r * Th.x) * inv1;
            S.y = (yi + 2.0 * L.y + 2.0 * r * Th.y) * inv1;
        } else if (j < MM) {
            int ii = j, jj = i - MM;
            size_t xo = base + (size_t)ii * NN + MM + jj;
            double2 L = g_Lamda[xo], Th = g_Theta[xo];
            double yr = (double)Yr[(size_t)b * MM * MM + ii * MM + jj];
            double yi = (double)Yi[(size_t)b * MM * MM + ii * MM + jj];
            S.x =  (yr + 2.0 * L.x + 2.0 * r * Th.x) * inv1;
            S.y = -((yi + 2.0 * L.y + 2.0 * r * Th.y) * inv1);
        } else {
            double2 L = g_Lamda[base + idx], Th = g_Theta[base + idx];
            S.x = L.x * invr + Th.x - ((i == j) ? tdr : 0.0);
            S.y = L.y * invr + Th.y;
        }
        g_S[base + idx] = S;
        double2 L = g_Lamda[base + idx];
        g_Af[base + idx] = make_float2((float)(S.x - L.x * invr),
                                       (float)(S.y - L.y * invr));
    }
}

// ---------------- fp32 parallel Hermitian Jacobi, A in smem -----------------
__device__ __forceinline__ double block_reduce(double v, double* sred, int tid) {
    for (int o = 16; o; o >>= 1) v += __shfl_down_sync(0xffffffffu, v, o);
    if ((tid & 31) == 0) sred[tid >> 5] = v;
    __syncthreads();
    if (tid < 32) {
        double x = sred[tid];
        for (int o = 16; o; o >>= 1) x += __shfl_down_sync(0xffffffffu, x, o);
        if (tid == 0) sred[0] = x;
    }
    __syncthreads();
    double r = sred[0];
    __syncthreads();
    return r;
}

__global__ __launch_bounds__(1024, 1) void jacobi_kernel() {
    extern __shared__ float2 sA[];   // [128][SROW]
    int b = blockIdx.x, tid = threadIdx.x;
    const float2* __restrict__ Ag = g_Af + (size_t)b * NN * NN;
    float2* __restrict__ VT = g_Vf + (size_t)b * NN * NN;

    __shared__ int   sp[64], sq[64];
    __shared__ float scc[64], ssr[64], ssi[64];
    __shared__ double sred[32];

    for (int idx = tid; idx < NN * NN; idx += 1024) {
        int i = idx >> 7, j = idx & 127;
        sA[i * SROW + j] = Ag[idx];
        VT[idx] = make_float2(i == j ? 1.0f : 0.0f, 0.0f);
    }
    __syncthreads();

    double acc = 0.0;
    for (int idx = tid; idx < NN * NN; idx += 1024) {
        int i = idx >> 7, j = idx & 127;
        float2 a = sA[i * SROW + j];
        acc += (double)a.x * a.x + (double)a.y * a.y;
    }
    double tol2 = block_reduce(acc, sred, tid) * 1e-11;

    for (int sweep = 0; sweep < 14; ++sweep) {
        acc = 0.0;
        for (int idx = tid; idx < NN * NN; idx += 1024) {
            int i = idx >> 7, j = idx & 127;
            if (i != j) {
                float2 a = sA[i * SROW + j];
                acc += (double)a.x * a.x + (double)a.y * a.y;
            }
        }
        double off2 = block_reduce(acc, sred, tid);
        if (off2 <= tol2) break;

        for (int r = 0; r < NN - 1; ++r) {
            if (tid < 64) {
                int p, q;
                if (tid == 0) { p = NN - 1; q = r % (NN - 1); }
                else {
                    p = (r + tid) % (NN - 1);
                    q = (r - tid + 2 * (NN - 1)) % (NN - 1);
                }
                sp[tid] = p; sq[tid] = q;
                float app = sA[p * SROW + p].x;
                float aqq = sA[q * SROW + q].x;
                float2 apq = sA[p * SROW + q];
                float mag2 = apq.x * apq.x + apq.y * apq.y;
                float c = 1.0f, zr = 0.0f, zi = 0.0f;
                if (mag2 > 1e-28f) {
                    float mag = sqrtf(mag2);
                    float th  = (aqq - app) / (2.0f * mag);
                    float rt  = sqrtf(th * th + 1.0f);
                    float tt  = (th >= 0.0f) ? 1.0f / (th + rt) : -1.0f / (rt - th);
                    c = rsqrtf(1.0f + tt * tt);
                    float sg = tt * c / mag;
                    zr = sg * apq.x; zi = sg * apq.y;
                }
                scc[tid] = c; ssr[tid] = zr; ssi[tid] = zi;
            }
            __syncthreads();
            // phase B: row mixing  B = R^H A
            for (int item = tid; item < 64 * NN; item += 1024) {
                int m = item >> 7, j = item & 127;
                int p = sp[m], q = sq[m];
                float c = scc[m], zr = ssr[m], zi = ssi[m];
                float2 ap = sA[p * SROW + j], aq = sA[q * SROW + j];
                float2 np, nq;
                np.x = c * ap.x - (zr * aq.x - zi * aq.y);
                np.y = c * ap.y - (zr * aq.y + zi * aq.x);
                nq.x = (zr * ap.x + zi * ap.y) + c * aq.x;
                nq.y = (zr * ap.y - zi * ap.x) + c * aq.y;
                sA[p * SROW + j] = np;
                sA[q * SROW + j] = nq;
            }
            __syncthreads();
            // phase C: column mixing of A, and row mixing of VT (= V col mix)
            for (int item = tid; item < 64 * NN; item += 1024) {
                int m = item >> 7, i = item & 127;
                int p = sp[m], q = sq[m];
                float c = scc[m], zr = ssr[m], zi = ssi[m];
                float2 bp = sA[i * SROW + p], bq = sA[i * SROW + q];
                float2 np, nq;
                np.x = c * bp.x - (zr * bq.x + zi * bq.y);
                np.y = c * bp.y - (zr * bq.y - zi * bq.x);
                nq.x = (zr * bp.x - zi * bp.y) + c * bq.x;
                nq.y = (zr * bp.y + zi * bp.x) + c * bq.y;
                sA[i * SROW + p] = np; sA[i * SROW + q] = nq;
                float2 vp = VT[p * NN + i], vq = VT[q * NN + i];
                np.x = c * vp.x - (zr * vq.x + zi * vq.y);
                np.y = c * vp.y - (zr * vq.y - zi * vq.x);
                nq.x = (zr * vp.x - zi * vp.y) + c * vq.x;
                nq.y = (zr * vp.y + zi * vp.x) + c * vq.y;
                VT[p * NN + i] = np; VT[q * NN + i] = nq;
            }
            __syncthreads();
        }
    }
    if (tid < NN) g_w[b * NN + tid] = (double)sA[tid * SROW + tid].x;
}

// ------- rank eigenvalues ascending, shift by minv[rank], clip at 0 ---------
__global__ void rank_clip_kernel(int it) {
    int b = blockIdx.x, j = threadIdx.x;   // 128 threads
    __shared__ double w[NN];
    w[j] = g_w[b * NN + j];
    __syncthreads();
    double wj = w[j];
    int rank = 0;
    for (int k = 0; k < NN; ++k) {
        double wk = w[k];
        rank += (wk < wj) || (wk == wj && k < j);
    }
    double d = wj + g_minv[((size_t)it * NB + b) * NN + rank];
    g_sdf[b * NN + j] = (float)(d > 0.0 ? d : 0.0);
}

// ---- Sita = V diag(d) V^H (fp32) ; Theta = Sita ; Lamda += e*(Sita-S) ------
__global__ __launch_bounds__(256) void sita_update_kernel(const float* __restrict__ eta, int it) {
    int bid = blockIdx.x;
    int b  = bid >> 4;
    int ti = (bid >> 2) & 3, tj = bid & 3;
    double e = (double)eta[it];
    size_t base = (size_t)b * NN * NN;
    const float2* __restrict__ VT = g_Vf + base;

    __shared__ float2 As[32][33];
    __shared__ float2 Bs[32][33];
    int tx = threadIdx.x & 15, ty = threadIdx.x >> 4;
    int i0 = ti * 32, j0 = tj * 32;
    float2 acc[2][2];
    acc[0][0] = acc[0][1] = acc[1][0] = acc[1][1] = make_float2(0.0f, 0.0f);

    for (int k0 = 0; k0 < NN; k0 += 32) {
        for (int l = threadIdx.x; l < 32 * 32; l += 256) {
            int rr = l & 31, kk = l >> 5;
            float dk = g_sdf[b * NN + k0 + kk];
            float2 v = VT[(size_t)(k0 + kk) * NN + i0 + rr];   // V[i0+rr][k0+kk]
            As[rr][kk] = make_float2(v.x * dk, v.y * dk);
            Bs[rr][kk] = VT[(size_t)(k0 + kk) * NN + j0 + rr]; // V[j0+rr][k0+kk]
        }
        __syncthreads();
#pragma unroll 8
        for (int kk = 0; kk < 32; ++kk) {
            float2 a0 = As[ty][kk],      a1 = As[ty + 16][kk];
            float2 b0 = Bs[tx][kk],      b1 = Bs[tx + 16][kk];
            acc[0][0].x += a0.x * b0.x + a0.y * b0.y; acc[0][0].y += a0.y * b0.x - a0.x * b0.y;
            acc[0][1].x += a0.x * b1.x + a0.y * b1.y; acc[0][1].y += a0.y * b1.x - a0.x * b1.y;
            acc[1][0].x += a1.x * b0.x + a1.y * b0.y; acc[1][0].y += a1.y * b0.x - a1.x * b0.y;
            acc[1][1].x += a1.x * b1.x + a1.y * b1.y; acc[1][1].y += a1.y * b1.x - a1.x * b1.y;
        }
        __syncthreads();
    }
    for (int r2 = 0; r2 < 2; ++r2)
        for (int c2 = 0; c2 < 2; ++c2) {
            int gi = i0 + ty + 16 * r2, gj = j0 + tx + 16 * c2;
            size_t idx = base + (size_t)gi * NN + gj;
            float2 s = acc[r2][c2];
            g_Theta[idx] = make_double2((double)s.x, (double)s.y);
            double2 L = g_Lamda[idx];
            double2 S = g_S[idx];
            L.x += e * ((double)s.x - S.x);
            L.y += e * ((double)s.y - S.y);
            g_Lamda[idx] = L;
        }
}

// ---------------- output writers (dtype-adaptive) ---------------------------
__global__ void output_f32i_kernel(float* __restrict__ out, int out_elems) {
    int b = blockIdx.x, tid = threadIdx.x;   // 256
    const double2* T = g_T + (size_t)b * MM * MM;
    for (int idx = tid; idx < MM * MM; idx += 256) {
        double2 v = T[idx];
        size_t o = ((size_t)b * MM * MM + idx) * 2;
        if (o + 1 < (size_t)out_elems) {
            out[o]     = (float)v.x;
            out[o + 1] = (float)v.y;
        }
    }
    if (tid < MM) {
        int k = tid;
        double ax = 0.0, ay = 0.0;
        for (int i = k; i < MM; ++i) {
            double2 v = T[(size_t)i * MM + (i - k)];
            ax += v.x; ay += v.y;
        }
        double nk = 1.0 / (double)(MM - k);
        size_t o = 2 * (size_t)NB * MM * MM + ((size_t)b * MM + k) * 2;
        if (o + 1 < (size_t)out_elems) {
            out[o]     = (float)(ax * nk);
            out[o + 1] = (float)(ay * nk);
        }
    }
}

__global__ void output_f32r_kernel(float* __restrict__ out, int out_elems) {
    int b = blockIdx.x, tid = threadIdx.x;   // 256
    const double2* T = g_T + (size_t)b * MM * MM;
    for (int idx = tid; idx < MM * MM; idx += 256) {
        size_t o = (size_t)b * MM * MM + idx;
        if (o < (size_t)out_elems) out[o] = (float)T[idx].x;
    }
    if (tid < MM) {
        int k = tid;
        double ax = 0.0;
        for (int i = k; i < MM; ++i) ax += T[(size_t)i * MM + (i - k)].x;
        size_t o = (size_t)NB * MM * MM + (size_t)b * MM + k;
        if (o < (size_t)out_elems) out[o] = (float)(ax / (double)(MM - k));
    }
}

extern "C" void kernel_launch(void* const* d_in, const int* in_sizes, int n_in,
                              void* d_out, int out_size) {
    const float* Yr  = (const float*)d_in[0];
    const float* Yi  = (const float*)d_in[1];
    const float* rho = (const float*)d_in[2];
    const float* tau = (const float*)d_in[3];
    const float* eta = (const float*)d_in[4];

    const int JSMEM = NN * SROW * (int)sizeof(float2);  // 132096 B
    cudaFuncSetAttribute(jacobi_kernel,
                         cudaFuncAttributeMaxDynamicSharedMemorySize, JSMEM);

    zero_kernel<<<(NB * NN * NN + 255) / 256, 256>>>();
    minv_kernel<<<(KIT * NB * NN + 255) / 256, 256>>>();

    for (int it = 0; it < KIT; ++it) {
        prepare_kernel<<<NB, 256>>>(Yr, Yi, rho, tau, it);
        jacobi_kernel<<<NB, 1024, JSMEM>>>();
        rank_clip_kernel<<<NB, NN>>>(it);
        sita_update_kernel<<<NB * 16, 256>>>(eta, it);
    }

    const long long total_c = (long long)NB * MM * MM + (long long)NB * MM; // 266240
    if ((long long)out_size >= 2 * total_c) {
        output_f32i_kernel<<<NB, 256>>>((float*)d_out, out_size);
    } else {
        output_f32r_kernel<<<NB, 256>>>((float*)d_out, out_size);
    }
}

// round 14
// speedup vs baseline: 26.4320x; 1.5532x over previous
#include <cuda_runtime.h>
#include <math.h>

#define NB 64
#define MM 64
#define NN 128
#define KIT 10
#define SROW 129   // padded smem row stride (float2)

// ---------------- persistent device state ----------------------------------
__device__ double2 g_Theta[NB * NN * NN];   // fp64 ADMM state
__device__ double2 g_Lamda[NB * NN * NN];
__device__ double2 g_S[NB * NN * NN];       // StackM (fp64)
__device__ double2 g_T[NB * MM * MM];
__device__ float2  g_Af[NB * NN * NN];      // fp32 A (prepare output)
__device__ float2  g_P [NB * NN * NN];      // scratch: P = A * VT^T
__device__ float2  g_Bf[NB * NN * NN];      // jacobi input: B = V^H A V
__device__ float2  g_Uf[NB * NN * NN];      // jacobi output UT (U transposed)
__device__ float2  g_VT[2][NB * NN * NN];   // accumulated eigvecs, transposed, dbl-buffered
__device__ double  g_minv[KIT * NB * NN];
__device__ double  g_w[NB * NN];
__device__ float   g_sdf[NB * NN];

// ---------------- threefry2x32 (JAX-compatible) ----------------------------
__device__ __forceinline__ void tf2x32(unsigned k0, unsigned k1,
                                       unsigned &x0, unsigned &x1) {
    unsigned ks2 = k0 ^ k1 ^ 0x1BD11BDAu;
    x0 += k0; x1 += k1;
#define TF_ROT(x, d) (((x) << (d)) | ((x) >> (32 - (d))))
#define TF_RND(r) do { x0 += x1; x1 = TF_ROT(x1, r); x1 ^= x0; } while (0)
    TF_RND(13); TF_RND(15); TF_RND(26); TF_RND(6);
    x0 += k1;  x1 += ks2 + 1u;
    TF_RND(17); TF_RND(29); TF_RND(16); TF_RND(24);
    x0 += ks2; x1 += k0 + 2u;
    TF_RND(13); TF_RND(15); TF_RND(26); TF_RND(6);
    x0 += k0;  x1 += k1 + 3u;
    TF_RND(17); TF_RND(29); TF_RND(16); TF_RND(24);
    x0 += k1;  x1 += ks2 + 4u;
    TF_RND(13); TF_RND(15); TF_RND(26); TF_RND(6);
    x0 += ks2; x1 += k0 + 5u;
#undef TF_RND
#undef TF_ROT
}

__global__ void minv_kernel() {
    int idx = blockIdx.x * blockDim.x + threadIdx.x;
    if (idx >= KIT * NB * NN) return;
    int it = idx / (NB * NN);
    unsigned i = (unsigned)(idx % (NB * NN));
    unsigned k0 = 0u, k1 = (unsigned)it;
    tf2x32(0u, 42u, k0, k1);
    unsigned y0 = 0u, y1 = i;
    tf2x32(k0, k1, y0, y1);
    unsigned long long bits = ((unsigned long long)y0 << 32) | (unsigned long long)y1;
    unsigned long long fb = (bits >> 12) | 0x3FF0000000000000ULL;
    double f  = __longlong_as_double((long long)fb) - 1.0;
    double lo = __longlong_as_double((long long)0xBFEFFFFFFFFFFFFFULL);
    double u  = f * 2.0 + lo;
    u = fmax(lo, u);
    g_minv[idx] = 1.4142135623730951 * erfinv(u);
}

__global__ void zero_kernel() {
    int idx = blockIdx.x * blockDim.x + threadIdx.x;
    if (idx < NB * NN * NN) {
        g_Theta[idx] = make_double2(0.0, 0.0);
        g_Lamda[idx] = make_double2(0.0, 0.0);
        int i = (idx >> 7) & 127, j = idx & 127;
        g_VT[0][idx] = make_float2((i == j) ? 1.0f : 0.0f, 0.0f);
    }
}

// --------- per-iteration: StackM (g_S), T block, A_f32 = StackM - Lamda/r ---
__global__ void prepare_kernel(const float* __restrict__ Yr,
                               const float* __restrict__ Yi,
                               const float* __restrict__ rho,
                               const float* __restrict__ tau, int it) {
    int b = blockIdx.x;
    int tid = threadIdx.x;              // 256
    double r = (double)rho[it];
    double t = (double)tau[it];
    size_t base = (size_t)b * NN * NN;

    __shared__ double2 su[MM];
    if (tid < MM) {
        int k = tid;
        double ax = 0.0, ay = 0.0;
        for (int i = 0; i + k < MM; ++i) {
            double2 L  = g_Lamda[base + (size_t)i * NN + i + k];
            double2 Th = g_Theta[base + (size_t)i * NN + i + k];
            ax += L.x + r * Th.x;
            ay += L.y + r * Th.y;
        }
        if (k == 0) ax += -(t * 0.5) * (double)MM;
        double sc = (1.0 / (double)(MM - k)) / r;
        su[k] = make_double2(ax * sc, ay * sc);
    }
    __syncthreads();

    double inv1 = 1.0 / (1.0 + 2.0 * r);
    double invr = 1.0 / r;
    double tdr  = t / (2.0 * r);
    for (int idx = tid; idx < NN * NN; idx += blockDim.x) {
        int i = idx >> 7, j = idx & 127;
        double2 S;
        if (i < MM && j < MM) {
            S = (j >= i) ? su[j - i] : make_double2(su[i - j].x, -su[i - j].y);
            g_T[(size_t)b * MM * MM + i * MM + j] = S;
        } else if (i < MM) {
            int jj = j - MM;
            double2 L = g_Lamda[base + idx], Th = g_Theta[base + idx];
            double yr = (double)Yr[(size_t)b * MM * MM + i * MM + jj];
            double yi = (double)Yi[(size_t)b * MM * MM + i * MM + jj];
            S.x = (yr + 2.0 * L.x + 2.0 * r * Th.x) * inv1;
            S.y = (yi + 2.0 * L.y + 2.0 * r * Th.y) * inv1;
        } else if (j < MM) {
            int ii = j, jj = i - MM;
            size_t xo = base + (size_t)ii * NN + MM + jj;
            double2 L = g_Lamda[xo], Th = g_Theta[xo];
            double yr = (double)Yr[(size_t)b * MM * MM + ii * MM + jj];
            double yi = (double)Yi[(size_t)b * MM * MM + ii * MM + jj];
            S.x =  (yr + 2.0 * L.x + 2.0 * r * Th.x) * inv1;
            S.y = -((yi + 2.0 * L.y + 2.0 * r * Th.y) * inv1);
        } else {
            double2 L = g_Lamda[base + idx], Th = g_Theta[base + idx];
            S.x = L.x * invr + Th.x - ((i == j) ? tdr : 0.0);
            S.y = L.y * invr + Th.y;
        }
        g_S[base + idx] = S;
        double2 L = g_Lamda[base + idx];
        g_Af[base + idx] = make_float2((float)(S.x - L.x * invr),
                                       (float)(S.y - L.y * invr));
    }
}

// ---------------- tiled complex gemms (per-batch 128x128) -------------------
// NT: C[i][l] = sum_j A[i][j] * Bt[l][j]
__global__ __launch_bounds__(256) void gemm_nt_kernel(const float2* __restrict__ A,
                                                      const float2* __restrict__ Bt,
                                                      float2* __restrict__ C) {
    int bid = blockIdx.x;
    int b  = bid >> 4;
    int ti = (bid >> 2) & 3, tj = bid & 3;
    size_t base = (size_t)b * NN * NN;
    __shared__ float2 As[32][33];
    __shared__ float2 Bs[32][33];
    int tx = threadIdx.x & 15, ty = threadIdx.x >> 4;
    int i0 = ti * 32, j0 = tj * 32;
    float2 acc[2][2];
    acc[0][0] = acc[0][1] = acc[1][0] = acc[1][1] = make_float2(0.f, 0.f);
    for (int k0 = 0; k0 < NN; k0 += 32) {
        for (int l = threadIdx.x; l < 32 * 32; l += 256) {
            int rr = l >> 5, kk = l & 31;
            As[rr][kk] = A [base + (size_t)(i0 + rr) * NN + k0 + kk];
            Bs[rr][kk] = Bt[base + (size_t)(j0 + rr) * NN + k0 + kk];
        }
        __syncthreads();
#pragma unroll 8
        for (int kk = 0; kk < 32; ++kk) {
            float2 a0 = As[ty][kk], a1 = As[ty + 16][kk];
            float2 b0 = Bs[tx][kk], b1 = Bs[tx + 16][kk];
            acc[0][0].x += a0.x * b0.x - a0.y * b0.y; acc[0][0].y += a0.x * b0.y + a0.y * b0.x;
            acc[0][1].x += a0.x * b1.x - a0.y * b1.y; acc[0][1].y += a0.x * b1.y + a0.y * b1.x;
            acc[1][0].x += a1.x * b0.x - a1.y * b0.y; acc[1][0].y += a1.x * b0.y + a1.y * b0.x;
            acc[1][1].x += a1.x * b1.x - a1.y * b1.y; acc[1][1].y += a1.x * b1.y + a1.y * b1.x;
        }
        __syncthreads();
    }
    for (int r2 = 0; r2 < 2; ++r2)
        for (int c2 = 0; c2 < 2; ++c2)
            C[base + (size_t)(i0 + ty + 16 * r2) * NN + j0 + tx + 16 * c2] = acc[r2][c2];
}

// NN: C[k][l] = sum_i opA(A[k][i]) * B[i][l]   (opA = conj if CONJA)
template <bool CONJA>
__global__ __launch_bounds__(256) void gemm_nn_kernel(const float2* __restrict__ A,
                                                      const float2* __restrict__ B,
                                                      float2* __restrict__ C) {
    int bid = blockIdx.x;
    int b  = bid >> 4;
    int ti = (bid >> 2) & 3, tj = bid & 3;
    size_t base = (size_t)b * NN * NN;
    __shared__ float2 As[32][33];
    __shared__ float2 Bs[32][33];
    int tx = threadIdx.x & 15, ty = threadIdx.x >> 4;
    int i0 = ti * 32, j0 = tj * 32;
    float2 acc[2][2];
    acc[0][0] = acc[0][1] = acc[1][0] = acc[1][1] = make_float2(0.f, 0.f);
    for (int k0 = 0; k0 < NN; k0 += 32) {
        for (int l = threadIdx.x; l < 32 * 32; l += 256) {
            int rr = l >> 5, kk = l & 31;
            As[rr][kk] = A[base + (size_t)(i0 + rr) * NN + k0 + kk];   // As[row][inner]
            Bs[rr][kk] = B[base + (size_t)(k0 + rr) * NN + j0 + kk];   // Bs[inner][col]
        }
        __syncthreads();
#pragma unroll 8
        for (int kk = 0; kk < 32; ++kk) {
            float2 a0 = As[ty][kk], a1 = As[ty + 16][kk];
            float2 b0 = Bs[kk][tx], b1 = Bs[kk][tx + 16];
            if (CONJA) {
                acc[0][0].x += a0.x * b0.x + a0.y * b0.y; acc[0][0].y += a0.x * b0.y - a0.y * b0.x;
                acc[0][1].x += a0.x * b1.x + a0.y * b1.y; acc[0][1].y += a0.x * b1.y - a0.y * b1.x;
                acc[1][0].x += a1.x * b0.x + a1.y * b0.y; acc[1][0].y += a1.x * b0.y - a1.y * b0.x;
                acc[1][1].x += a1.x * b1.x + a1.y * b1.y; acc[1][1].y += a1.x * b1.y - a1.y * b1.x;
            } else {
                acc[0][0].x += a0.x * b0.x - a0.y * b0.y; acc[0][0].y += a0.x * b0.y + a0.y * b0.x;
                acc[0][1].x += a0.x * b1.x - a0.y * b1.y; acc[0][1].y += a0.x * b1.y + a0.y * b1.x;
                acc[1][0].x += a1.x * b0.x - a1.y * b0.y; acc[1][0].y += a1.x * b0.y + a1.y * b0.x;
                acc[1][1].x += a1.x * b1.x - a1.y * b1.y; acc[1][1].y += a1.x * b1.y + a1.y * b1.x;
            }
        }
        __syncthreads();
    }
    for (int r2 = 0; r2 < 2; ++r2)
        for (int c2 = 0; c2 < 2; ++c2)
            C[base + (size_t)(i0 + ty + 16 * r2) * NN + j0 + tx + 16 * c2] = acc[r2][c2];
}

// ---------------- fp32 parallel Hermitian Jacobi, B in smem -----------------
__device__ __forceinline__ double block_reduce(double v, double* sred, int tid) {
    for (int o = 16; o; o >>= 1) v += __shfl_down_sync(0xffffffffu, v, o);
    if ((tid & 31) == 0) sred[tid >> 5] = v;
    __syncthreads();
    if (tid < 32) {
        double x = sred[tid];
        for (int o = 16; o; o >>= 1) x += __shfl_down_sync(0xffffffffu, x, o);
        if (tid == 0) sred[0] = x;
    }
    __syncthreads();
    double r = sred[0];
    __syncthreads();
    return r;
}

__global__ __launch_bounds__(1024, 1) void jacobi_kernel() {
    extern __shared__ float2 sA[];   // [128][SROW]
    int b = blockIdx.x, tid = threadIdx.x;
    const float2* __restrict__ Bg = g_Bf + (size_t)b * NN * NN;
    float2* __restrict__ UT = g_Uf + (size_t)b * NN * NN;

    __shared__ int   sp[64], sq[64];
    __shared__ float scc[64], ssr[64], ssi[64];
    __shared__ double sred[32];

    for (int idx = tid; idx < NN * NN; idx += 1024) {
        int i = idx >> 7, j = idx & 127;
        sA[i * SROW + j] = Bg[idx];
        UT[idx] = make_float2(i == j ? 1.0f : 0.0f, 0.0f);
    }
    __syncthreads();

    double acc = 0.0;
    for (int idx = tid; idx < NN * NN; idx += 1024) {
        int i = idx >> 7, j = idx & 127;
        float2 a = sA[i * SROW + j];
        acc += (double)a.x * a.x + (double)a.y * a.y;
    }
    double tol2 = block_reduce(acc, sred, tid) * 1e-11;

    for (int sweep = 0; sweep < 14; ++sweep) {
        acc = 0.0;
        for (int idx = tid; idx < NN * NN; idx += 1024) {
            int i = idx >> 7, j = idx & 127;
            if (i != j) {
                float2 a = sA[i * SROW + j];
                acc += (double)a.x * a.x + (double)a.y * a.y;
            }
        }
        double off2 = block_reduce(acc, sred, tid);
        if (off2 <= tol2) break;

        for (int r = 0; r < NN - 1; ++r) {
            if (tid < 64) {
                int p, q;
                if (tid == 0) { p = NN - 1; q = r % (NN - 1); }
                else {
                    p = (r + tid) % (NN - 1);
                    q = (r - tid + 2 * (NN - 1)) % (NN - 1);
                }
                sp[tid] = p; sq[tid] = q;
                float app = sA[p * SROW + p].x;
                float aqq = sA[q * SROW + q].x;
                float2 apq = sA[p * SROW + q];
                float mag2 = apq.x * apq.x + apq.y * apq.y;
                float c = 1.0f, zr = 0.0f, zi = 0.0f;
                if (mag2 > 1e-28f) {
                    float mag = sqrtf(mag2);
                    float th  = (aqq - app) / (2.0f * mag);
                    float rt  = sqrtf(th * th + 1.0f);
                    float tt  = (th >= 0.0f) ? 1.0f / (th + rt) : -1.0f / (rt - th);
                    c = rsqrtf(1.0f + tt * tt);
                    float sg = tt * c / mag;
                    zr = sg * apq.x; zi = sg * apq.y;
                }
                scc[tid] = c; ssr[tid] = zr; ssi[tid] = zi;
            }
            __syncthreads();
            // phase B: row mixing  B = R^H A
            for (int item = tid; item < 64 * NN; item += 1024) {
                int m = item >> 7, j = item & 127;
                int p = sp[m], q = sq[m];
                float c = scc[m], zr = ssr[m], zi = ssi[m];
                float2 ap = sA[p * SROW + j], aq = sA[q * SROW + j];
                float2 np, nq;
                np.x = c * ap.x - (zr * aq.x - zi * aq.y);
                np.y = c * ap.y - (zr * aq.y + zi * aq.x);
                nq.x = (zr * ap.x + zi * ap.y) + c * aq.x;
                nq.y = (zr * ap.y - zi * ap.x) + c * aq.y;
                sA[p * SROW + j] = np;
                sA[q * SROW + j] = nq;
            }
            __syncthreads();
            // phase C: column mixing of A, and row mixing of UT
            for (int item = tid; item < 64 * NN; item += 1024) {
                int m = item >> 7, i = item & 127;
                int p = sp[m], q = sq[m];
                float c = scc[m], zr = ssr[m], zi = ssi[m];
                float2 bp = sA[i * SROW + p], bq = sA[i * SROW + q];
                float2 np, nq;
                np.x = c * bp.x - (zr * bq.x + zi * bq.y);
                np.y = c * bp.y - (zr * bq.y - zi * bq.x);
                nq.x = (zr * bp.x - zi * bp.y) + c * bq.x;
                nq.y = (zr * bp.y + zi * bp.x) + c * bq.y;
                sA[i * SROW + p] = np; sA[i * SROW + q] = nq;
                float2 vp = UT[p * NN + i], vq = UT[q * NN + i];
                np.x = c * vp.x - (zr * vq.x + zi * vq.y);
                np.y = c * vp.y - (zr * vq.y - zi * vq.x);
                nq.x = (zr * vp.x - zi * vp.y) + c * vq.x;
                nq.y = (zr * vp.y + zi * vp.x) + c * vq.y;
                UT[p * NN + i] = np; UT[q * NN + i] = nq;
            }
            __syncthreads();
        }
    }
    if (tid < NN) g_w[b * NN + tid] = (double)sA[tid * SROW + tid].x;
}

// ------- rank eigenvalues ascending, shift by minv[rank], clip at 0 ---------
__global__ void rank_clip_kernel(int it) {
    int b = blockIdx.x, j = threadIdx.x;   // 128 threads
    __shared__ double w[NN];
    w[j] = g_w[b * NN + j];
    __syncthreads();
    double wj = w[j];
    int rank = 0;
    for (int k = 0; k < NN; ++k) {
        double wk = w[k];
        rank += (wk < wj) || (wk == wj && k < j);
    }
    double d = wj + g_minv[((size_t)it * NB + b) * NN + rank];
    g_sdf[b * NN + j] = (float)(d > 0.0 ? d : 0.0);
}

// ---- Sita = V diag(d) V^H (fp32) ; Theta = Sita ; Lamda += e*(Sita-S) ------
__global__ __launch_bounds__(256) void sita_update_kernel(const float2* __restrict__ VTall,
                                                          const float* __restrict__ eta, int it) {
    int bid = blockIdx.x;
    int b  = bid >> 4;
    int ti = (bid >> 2) & 3, tj = bid & 3;
    double e = (double)eta[it];
    size_t base = (size_t)b * NN * NN;
    const float2* __restrict__ VT = VTall + base;

    __shared__ float2 As[32][33];
    __shared__ float2 Bs[32][33];
    int tx = threadIdx.x & 15, ty = threadIdx.x >> 4;
    int i0 = ti * 32, j0 = tj * 32;
    float2 acc[2][2];
    acc[0][0] = acc[0][1] = acc[1][0] = acc[1][1] = make_float2(0.0f, 0.0f);

    for (int k0 = 0; k0 < NN; k0 += 32) {
        for (int l = threadIdx.x; l < 32 * 32; l += 256) {
            int rr = l & 31, kk = l >> 5;
            float dk = g_sdf[b * NN + k0 + kk];
            float2 v = VT[(size_t)(k0 + kk) * NN + i0 + rr];   // V[i0+rr][k0+kk]
            As[rr][kk] = make_float2(v.x * dk, v.y * dk);
            Bs[rr][kk] = VT[(size_t)(k0 + kk) * NN + j0 + rr]; // V[j0+rr][k0+kk]
        }
        __syncthreads();
#pragma unroll 8
        for (int kk = 0; kk < 32; ++kk) {
            float2 a0 = As[ty][kk],      a1 = As[ty + 16][kk];
            float2 b0 = Bs[tx][kk],      b1 = Bs[tx + 16][kk];
            acc[0][0].x += a0.x * b0.x + a0.y * b0.y; acc[0][0].y += a0.y * b0.x - a0.x * b0.y;
            acc[0][1].x += a0.x * b1.x + a0.y * b1.y; acc[0][1].y += a0.y * b1.x - a0.x * b1.y;
            acc[1][0].x += a1.x * b0.x + a1.y * b0.y; acc[1][0].y += a1.y * b0.x - a1.x * b0.y;
            acc[1][1].x += a1.x * b1.x + a1.y * b1.y; acc[1][1].y += a1.y * b1.x - a1.x * b1.y;
        }
        __syncthreads();
    }
    for (int r2 = 0; r2 < 2; ++r2)
        for (int c2 = 0; c2 < 2; ++c2) {
            int gi = i0 + ty + 16 * r2, gj = j0 + tx + 16 * c2;
            size_t idx = base + (size_t)gi * NN + gj;
            float2 s = acc[r2][c2];
            g_Theta[idx] = make_double2((double)s.x, (double)s.y);
            double2 L = g_Lamda[idx];
            double2 S = g_S[idx];
            L.x += e * ((double)s.x - S.x);
            L.y += e * ((double)s.y - S.y);
            g_Lamda[idx] = L;
        }
}

// ---------------- output writers (dtype-adaptive) ---------------------------
__global__ void output_f32i_kernel(float* __restrict__ out, int out_elems) {
    int b = blockIdx.x, tid = threadIdx.x;   // 256
    const double2* T = g_T + (size_t)b * MM * MM;
    for (int idx = tid; idx < MM * MM; idx += 256) {
        double2 v = T[idx];
        size_t o = ((size_t)b * MM * MM + idx) * 2;
        if (o + 1 < (size_t)out_elems) {
            out[o]     = (float)v.x;
            out[o + 1] = (float)v.y;
        }
    }
    if (tid < MM) {
        int k = tid;
        double ax = 0.0, ay = 0.0;
        for (int i = k; i < MM; ++i) {
            double2 v = T[(size_t)i * MM + (i - k)];
            ax += v.x; ay += v.y;
        }
        double nk = 1.0 / (double)(MM - k);
        size_t o = 2 * (size_t)NB * MM * MM + ((size_t)b * MM + k) * 2;
        if (o + 1 < (size_t)out_elems) {
            out[o]     = (float)(ax * nk);
            out[o + 1] = (float)(ay * nk);
        }
    }
}

__global__ void output_f32r_kernel(float* __restrict__ out, int out_elems) {
    int b = blockIdx.x, tid = threadIdx.x;   // 256
    const double2* T = g_T + (size_t)b * MM * MM;
    for (int idx = tid; idx < MM * MM; idx += 256) {
        size_t o = (size_t)b * MM * MM + idx;
        if (o < (size_t)out_elems) out[o] = (float)T[idx].x;
    }
    if (tid < MM) {
        int k = tid;
        double ax = 0.0;
        for (int i = k; i < MM; ++i) ax += T[(size_t)i * MM + (i - k)].x;
        size_t o = (size_t)NB * MM * MM + (size_t)b * MM + k;
        if (o < (size_t)out_elems) out[o] = (float)(ax / (double)(MM - k));
    }
}

extern "C" void kernel_launch(void* const* d_in, const int* in_sizes, int n_in,
                              void* d_out, int out_size) {
    const float* Yr  = (const float*)d_in[0];
    const float* Yi  = (const float*)d_in[1];
    const float* rho = (const float*)d_in[2];
    const float* tau = (const float*)d_in[3];
    const float* eta = (const float*)d_in[4];

    static bool s_init = false;
    static float2 *s_Af, *s_P, *s_Bf, *s_Uf, *s_VT0;
    if (!s_init) {
        const int JSMEM = NN * SROW * (int)sizeof(float2);  // 132096 B
        cudaFuncSetAttribute(jacobi_kernel,
                             cudaFuncAttributeMaxDynamicSharedMemorySize, JSMEM);
        void* p;
        cudaGetSymbolAddress(&p, g_Af);  s_Af  = (float2*)p;
        cudaGetSymbolAddress(&p, g_P);   s_P   = (float2*)p;
        cudaGetSymbolAddress(&p, g_Bf);  s_Bf  = (float2*)p;
        cudaGetSymbolAddress(&p, g_Uf);  s_Uf  = (float2*)p;
        cudaGetSymbolAddress(&p, g_VT);  s_VT0 = (float2*)p;
        s_init = true;
    }
    const int JSMEM = NN * SROW * (int)sizeof(float2);
    const size_t VTSZ = (size_t)NB * NN * NN;

    zero_kernel<<<(NB * NN * NN + 255) / 256, 256>>>();
    minv_kernel<<<(KIT * NB * NN + 255) / 256, 256>>>();

    for (int it = 0; it < KIT; ++it) {
        float2* VTsrc = s_VT0 + (size_t)(it & 1) * VTSZ;
        float2* VTdst = s_VT0 + (size_t)((it + 1) & 1) * VTSZ;

        prepare_kernel<<<NB, 256>>>(Yr, Yi, rho, tau, it);
        // warm start: B = V_prev^H A V_prev
        gemm_nt_kernel<<<NB * 16, 256>>>(s_Af, VTsrc, s_P);           // P = A * VT^T
        gemm_nn_kernel<true><<<NB * 16, 256>>>(VTsrc, s_P, s_Bf);     // B = conj(VT) * P
        jacobi_kernel<<<NB, 1024, JSMEM>>>();
        rank_clip_kernel<<<NB, NN>>>(it);
        gemm_nn_kernel<false><<<NB * 16, 256>>>(s_Uf, VTsrc, VTdst);  // VT_new = UT * VT_prev
        sita_update_kernel<<<NB * 16, 256>>>(VTdst, eta, it);
    }

    const long long total_c = (long long)NB * MM * MM + (long long)NB * MM; // 266240
    if ((long long)out_size >= 2 * total_c) {
        output_f32i_kernel<<<NB, 256>>>((float*)d_out, out_size);
    } else {
        output_f32r_kernel<<<NB, 256>>>((float*)d_out, out_size);
    }
}

// round 15
// speedup vs baseline: 33.2791x; 1.2590x over previous
#include <cuda_runtime.h>
#include <math.h>

#define NB 64
#define MM 64
#define NN 128
#define KIT 10
#define SROW 129   // padded smem row stride (float2)

// ---------------- persistent device state ----------------------------------
__device__ double2 g_Theta[NB * NN * NN];   // fp64 ADMM state
__device__ double2 g_Lamda[NB * NN * NN];
__device__ double2 g_S[NB * NN * NN];       // StackM (fp64)
__device__ double2 g_T[NB * MM * MM];
__device__ float2  g_Af[NB * NN * NN];      // fp32 A (prepare output)
__device__ float2  g_P [NB * NN * NN];      // scratch: warm-start P, then fp32 Sita
__device__ float2  g_Bf[NB * NN * NN];      // jacobi input: B = V^H A V
__device__ float2  g_Uf[NB * NN * NN];      // jacobi output UT (U transposed)
__device__ float2  g_VT[2][NB * NN * NN];   // accumulated eigvecs, transposed, dbl-buffered
__device__ double  g_minv[KIT * NB * NN];
__device__ double  g_w[NB * NN];
__device__ float   g_sdf[NB * NN];

// ---------------- threefry2x32 (JAX-compatible) ----------------------------
__device__ __forceinline__ void tf2x32(unsigned k0, unsigned k1,
                                       unsigned &x0, unsigned &x1) {
    unsigned ks2 = k0 ^ k1 ^ 0x1BD11BDAu;
    x0 += k0; x1 += k1;
#define TF_ROT(x, d) (((x) << (d)) | ((x) >> (32 - (d))))
#define TF_RND(r) do { x0 += x1; x1 = TF_ROT(x1, r); x1 ^= x0; } while (0)
    TF_RND(13); TF_RND(15); TF_RND(26); TF_RND(6);
    x0 += k1;  x1 += ks2 + 1u;
    TF_RND(17); TF_RND(29); TF_RND(16); TF_RND(24);
    x0 += ks2; x1 += k0 + 2u;
    TF_RND(13); TF_RND(15); TF_RND(26); TF_RND(6);
    x0 += k0;  x1 += k1 + 3u;
    TF_RND(17); TF_RND(29); TF_RND(16); TF_RND(24);
    x0 += k1;  x1 += ks2 + 4u;
    TF_RND(13); TF_RND(15); TF_RND(26); TF_RND(6);
    x0 += ks2; x1 += k0 + 5u;
#undef TF_RND
#undef TF_ROT
}

__global__ void minv_kernel() {
    int idx = blockIdx.x * blockDim.x + threadIdx.x;
    if (idx >= KIT * NB * NN) return;
    int it = idx / (NB * NN);
    unsigned i = (unsigned)(idx % (NB * NN));
    unsigned k0 = 0u, k1 = (unsigned)it;
    tf2x32(0u, 42u, k0, k1);
    unsigned y0 = 0u, y1 = i;
    tf2x32(k0, k1, y0, y1);
    unsigned long long bits = ((unsigned long long)y0 << 32) | (unsigned long long)y1;
    unsigned long long fb = (bits >> 12) | 0x3FF0000000000000ULL;
    double f  = __longlong_as_double((long long)fb) - 1.0;
    double lo = __longlong_as_double((long long)0xBFEFFFFFFFFFFFFFULL);
    double u  = f * 2.0 + lo;
    u = fmax(lo, u);
    g_minv[idx] = 1.4142135623730951 * erfinv(u);
}

__global__ void zero_kernel() {
    int idx = blockIdx.x * blockDim.x + threadIdx.x;
    if (idx < NB * NN * NN) {
        g_Theta[idx] = make_double2(0.0, 0.0);
        g_Lamda[idx] = make_double2(0.0, 0.0);
        int i = (idx >> 7) & 127, j = idx & 127;
        g_VT[0][idx] = make_float2((i == j) ? 1.0f : 0.0f, 0.0f);
    }
}

// --------- per-iteration: StackM (g_S), T block, A_f32 = StackM - Lamda/r ---
__global__ void prepare_kernel(const float* __restrict__ Yr,
                               const float* __restrict__ Yi,
                               const float* __restrict__ rho,
                               const float* __restrict__ tau, int it) {
    int b = blockIdx.x;
    int tid = threadIdx.x;              // 256
    double r = (double)rho[it];
    double t = (double)tau[it];
    size_t base = (size_t)b * NN * NN;

    __shared__ double2 su[MM];
    if (tid < MM) {
        int k = tid;
        double ax = 0.0, ay = 0.0;
        for (int i = 0; i + k < MM; ++i) {
            double2 L  = g_Lamda[base + (size_t)i * NN + i + k];
            double2 Th = g_Theta[base + (size_t)i * NN + i + k];
            ax += L.x + r * Th.x;
            ay += L.y + r * Th.y;
        }
        if (k == 0) ax += -(t * 0.5) * (double)MM;
        double sc = (1.0 / (double)(MM - k)) / r;
        su[k] = make_double2(ax * sc, ay * sc);
    }
    __syncthreads();

    double inv1 = 1.0 / (1.0 + 2.0 * r);
    double invr = 1.0 / r;
    double tdr  = t / (2.0 * r);
    for (int idx = tid; idx < NN * NN; idx += blockDim.x) {
        int i = idx >> 7, j = idx & 127;
        double2 S;
        if (i < MM && j < MM) {
            S = (j >= i) ? su[j - i] : make_double2(su[i - j].x, -su[i - j].y);
            g_T[(size_t)b * MM * MM + i * MM + j] = S;
        } else if (i < MM) {
            int jj = j - MM;
            double2 L = g_Lamda[base + idx], Th = g_Theta[base + idx];
            double yr = (double)Yr[(size_t)b * MM * MM + i * MM + jj];
            double yi = (double)Yi[(size_t)b * MM * MM + i * MM + jj];
            S.x = (yr + 2.0 * L.x + 2.0 * r * Th.x) * inv1;
            S.y = (yi + 2.0 * L.y + 2.0 * r * Th.y) * inv1;
        } else if (j < MM) {
            int ii = j, jj = i - MM;
            size_t xo = base + (size_t)ii * NN + MM + jj;
            double2 L = g_Lamda[xo], Th = g_Theta[xo];
            double yr = (double)Yr[(size_t)b * MM * MM + ii * MM + jj];
            double yi = (double)Yi[(size_t)b * MM * MM + ii * MM + jj];
            S.x =  (yr + 2.0 * L.x + 2.0 * r * Th.x) * inv1;
            S.y = -((yi + 2.0 * L.y + 2.0 * r * Th.y) * inv1);
        } else {
            double2 L = g_Lamda[base + idx], Th = g_Theta[base + idx];
            S.x = L.x * invr + Th.x - ((i == j) ? tdr : 0.0);
            S.y = L.y * invr + Th.y;
        }
        g_S[base + idx] = S;
        double2 L = g_Lamda[base + idx];
        g_Af[base + idx] = make_float2((float)(S.x - L.x * invr),
                                       (float)(S.y - L.y * invr));
    }
}

// ---------------- tiled complex gemms (per-batch 128x128) -------------------
// NT: C[i][l] = sum_j A[i][j] * Bt[l][j]
__global__ __launch_bounds__(256) void gemm_nt_kernel(const float2* __restrict__ A,
                                                      const float2* __restrict__ Bt,
                                                      float2* __restrict__ C) {
    int bid = blockIdx.x;
    int b  = bid >> 4;
    int ti = (bid >> 2) & 3, tj = bid & 3;
    size_t base = (size_t)b * NN * NN;
    __shared__ float2 As[32][33];
    __shared__ float2 Bs[32][33];
    int tx = threadIdx.x & 15, ty = threadIdx.x >> 4;
    int i0 = ti * 32, j0 = tj * 32;
    float2 acc[2][2];
    acc[0][0] = acc[0][1] = acc[1][0] = acc[1][1] = make_float2(0.f, 0.f);
    for (int k0 = 0; k0 < NN; k0 += 32) {
        for (int l = threadIdx.x; l < 32 * 32; l += 256) {
            int rr = l >> 5, kk = l & 31;
            As[rr][kk] = A [base + (size_t)(i0 + rr) * NN + k0 + kk];
            Bs[rr][kk] = Bt[base + (size_t)(j0 + rr) * NN + k0 + kk];
        }
        __syncthreads();
#pragma unroll 8
        for (int kk = 0; kk < 32; ++kk) {
            float2 a0 = As[ty][kk], a1 = As[ty + 16][kk];
            float2 b0 = Bs[tx][kk], b1 = Bs[tx + 16][kk];
            acc[0][0].x += a0.x * b0.x - a0.y * b0.y; acc[0][0].y += a0.x * b0.y + a0.y * b0.x;
            acc[0][1].x += a0.x * b1.x - a0.y * b1.y; acc[0][1].y += a0.x * b1.y + a0.y * b1.x;
            acc[1][0].x += a1.x * b0.x - a1.y * b0.y; acc[1][0].y += a1.x * b0.y + a1.y * b0.x;
            acc[1][1].x += a1.x * b1.x - a1.y * b1.y; acc[1][1].y += a1.x * b1.y + a1.y * b1.x;
        }
        __syncthreads();
    }
    for (int r2 = 0; r2 < 2; ++r2)
        for (int c2 = 0; c2 < 2; ++c2)
            C[base + (size_t)(i0 + ty + 16 * r2) * NN + j0 + tx + 16 * c2] = acc[r2][c2];
}

// NN: C[k][l] = sum_i opA(A[k][i]) * B[i][l]   (opA = conj if CONJA)
template <bool CONJA>
__global__ __launch_bounds__(256) void gemm_nn_kernel(const float2* __restrict__ A,
                                                      const float2* __restrict__ B,
                                                      float2* __restrict__ C) {
    int bid = blockIdx.x;
    int b  = bid >> 4;
    int ti = (bid >> 2) & 3, tj = bid & 3;
    size_t base = (size_t)b * NN * NN;
    __shared__ float2 As[32][33];
    __shared__ float2 Bs[32][33];
    int tx = threadIdx.x & 15, ty = threadIdx.x >> 4;
    int i0 = ti * 32, j0 = tj * 32;
    float2 acc[2][2];
    acc[0][0] = acc[0][1] = acc[1][0] = acc[1][1] = make_float2(0.f, 0.f);
    for (int k0 = 0; k0 < NN; k0 += 32) {
        for (int l = threadIdx.x; l < 32 * 32; l += 256) {
            int rr = l >> 5, kk = l & 31;
            As[rr][kk] = A[base + (size_t)(i0 + rr) * NN + k0 + kk];
            Bs[rr][kk] = B[base + (size_t)(k0 + rr) * NN + j0 + kk];
        }
        __syncthreads();
#pragma unroll 8
        for (int kk = 0; kk < 32; ++kk) {
            float2 a0 = As[ty][kk], a1 = As[ty + 16][kk];
            float2 b0 = Bs[kk][tx], b1 = Bs[kk][tx + 16];
            if (CONJA) {
                acc[0][0].x += a0.x * b0.x + a0.y * b0.y; acc[0][0].y += a0.x * b0.y - a0.y * b0.x;
                acc[0][1].x += a0.x * b1.x + a0.y * b1.y; acc[0][1].y += a0.x * b1.y - a0.y * b1.x;
                acc[1][0].x += a1.x * b0.x + a1.y * b0.y; acc[1][0].y += a1.x * b0.y - a1.y * b0.x;
                acc[1][1].x += a1.x * b1.x + a1.y * b1.y; acc[1][1].y += a1.x * b1.y - a1.y * b1.x;
            } else {
                acc[0][0].x += a0.x * b0.x - a0.y * b0.y; acc[0][0].y += a0.x * b0.y + a0.y * b0.x;
                acc[0][1].x += a0.x * b1.x - a0.y * b1.y; acc[0][1].y += a0.x * b1.y + a0.y * b1.x;
                acc[1][0].x += a1.x * b0.x - a1.y * b0.y; acc[1][0].y += a1.x * b0.y + a1.y * b0.x;
                acc[1][1].x += a1.x * b1.x - a1.y * b1.y; acc[1][1].y += a1.x * b1.y + a1.y * b1.x;
            }
        }
        __syncthreads();
    }
    for (int r2 = 0; r2 < 2; ++r2)
        for (int c2 = 0; c2 < 2; ++c2)
            C[base + (size_t)(i0 + ty + 16 * r2) * NN + j0 + tx + 16 * c2] = acc[r2][c2];
}

// ---------------- fp32 parallel Hermitian Jacobi, fused 2x2-block update ----
__device__ __forceinline__ double block_reduce(double v, double* sred, int tid) {
    for (int o = 16; o; o >>= 1) v += __shfl_down_sync(0xffffffffu, v, o);
    if ((tid & 31) == 0) sred[tid >> 5] = v;
    __syncthreads();
    if (tid < 32) {
        double x = sred[tid];
        for (int o = 16; o; o >>= 1) x += __shfl_down_sync(0xffffffffu, x, o);
        if (tid == 0) sred[0] = x;
    }
    __syncthreads();
    double r = sred[0];
    __syncthreads();
    return r;
}

__global__ __launch_bounds__(1024, 1) void jacobi_kernel() {
    extern __shared__ float2 sA[];   // [128][SROW]
    int b = blockIdx.x, tid = threadIdx.x;
    const float2* __restrict__ Bg = g_Bf + (size_t)b * NN * NN;
    float2* __restrict__ UT = g_Uf + (size_t)b * NN * NN;

    __shared__ int   sp[64], sq[64], striv[64];
    __shared__ float scc[64], ssr[64], ssi[64];
    __shared__ double sred[32];

    // load with Hermitization: sA = (B + B^H)/2
    for (int idx = tid; idx < NN * NN; idx += 1024) {
        int i = idx >> 7, j = idx & 127;
        float2 bij = Bg[idx];
        float2 bji = Bg[(size_t)j * NN + i];
        sA[i * SROW + j] = make_float2(0.5f * (bij.x + bji.x),
                                       0.5f * (bij.y - bji.y));
        UT[idx] = make_float2(i == j ? 1.0f : 0.0f, 0.0f);
    }
    __syncthreads();

    double acc = 0.0;
    for (int idx = tid; idx < NN * NN; idx += 1024) {
        int i = idx >> 7, j = idx & 127;
        float2 a = sA[i * SROW + j];
        acc += (double)a.x * a.x + (double)a.y * a.y;
    }
    double tol2 = block_reduce(acc, sred, tid) * 2e-13;
    float sthr = (float)(tol2 * (1.0 / 8192.0));   // per-pair skip threshold

    for (int sweep = 0; sweep < 16; ++sweep) {
        acc = 0.0;
        for (int idx = tid; idx < NN * NN; idx += 1024) {
            int i = idx >> 7, j = idx & 127;
            if (i != j) {
                float2 a = sA[i * SROW + j];
                acc += (double)a.x * a.x + (double)a.y * a.y;
            }
        }
        double off2 = block_reduce(acc, sred, tid);
        if (off2 <= tol2) break;

        for (int r = 0; r < NN - 1; ++r) {
            if (tid < 64) {
                int p, q;
                if (tid == 0) { p = NN - 1; q = r % (NN - 1); }
                else {
                    p = (r + tid) % (NN - 1);
                    q = (r - tid + 2 * (NN - 1)) % (NN - 1);
                }
                sp[tid] = p; sq[tid] = q;
                float app = sA[p * SROW + p].x;
                float aqq = sA[q * SROW + q].x;
                float2 apq = sA[p * SROW + q];
                float mag2 = apq.x * apq.x + apq.y * apq.y;
                float c = 1.0f, zr = 0.0f, zi = 0.0f;
                int trivial = 1;
                if (mag2 > sthr && mag2 > 1e-28f) {
                    trivial = 0;
                    float mag = sqrtf(mag2);
                    float th  = (aqq - app) / (2.0f * mag);
                    float rt  = sqrtf(th * th + 1.0f);
                    float tt  = (th >= 0.0f) ? 1.0f / (th + rt) : -1.0f / (rt - th);
                    c = rsqrtf(1.0f + tt * tt);
                    float sg = tt * c / mag;
                    zr = sg * apq.x; zi = sg * apq.y;
                }
                scc[tid] = c; ssr[tid] = zr; ssi[tid] = zi; striv[tid] = trivial;
            }
            __syncthreads();

            // fused update: A' = R^H A R on disjoint 2x2 blocks (mi, mj)
            for (int t = tid; t < 64 * 64; t += 1024) {
                int mi = t >> 6, mj = t & 63;
                if (striv[mi] && striv[mj]) continue;
                int pi = sp[mi], qi = sq[mi], pj = sp[mj], qj = sq[mj];
                float ci = scc[mi], zri = ssr[mi], zii = ssi[mi];
                float cj = scc[mj], zrj = ssr[mj], zij = ssi[mj];
                float2 app = sA[pi * SROW + pj], apq = sA[pi * SROW + qj];
                float2 aqp = sA[qi * SROW + pj], aqq = sA[qi * SROW + qj];
                // left rotation (rows pi, qi)
                float2 b_pp, b_qp, b_pq, b_qq;
                b_pp.x = ci * app.x - (zri * aqp.x - zii * aqp.y);
                b_pp.y = ci * app.y - (zri * aqp.y + zii * aqp.x);
                b_qp.x = (zri * app.x + zii * app.y) + ci * aqp.x;
                b_qp.y = (zri * app.y - zii * app.x) + ci * aqp.y;
                b_pq.x = ci * apq.x - (zri * aqq.x - zii * aqq.y);
                b_pq.y = ci * apq.y - (zri * aqq.y + zii * aqq.x);
                b_qq.x = (zri * apq.x + zii * apq.y) + ci * aqq.x;
                b_qq.y = (zri * apq.y - zii * apq.x) + ci * aqq.y;
                // right rotation (cols pj, qj)
                float2 n_pp, n_pq, n_qp, n_qq;
                n_pp.x = cj * b_pp.x - (zrj * b_pq.x + zij * b_pq.y);
                n_pp.y = cj * b_pp.y - (zrj * b_pq.y - zij * b_pq.x);
                n_pq.x = (zrj * b_pp.x - zij * b_pp.y) + cj * b_pq.x;
                n_pq.y = (zrj * b_pp.y + zij * b_pp.x) + cj * b_pq.y;
                n_qp.x = cj * b_qp.x - (zrj * b_qq.x + zij * b_qq.y);
                n_qp.y = cj * b_qp.y - (zrj * b_qq.y - zij * b_qq.x);
                n_qq.x = (zrj * b_qp.x - zij * b_qp.y) + cj * b_qq.x;
                n_qq.y = (zrj * b_qp.y + zij * b_qp.x) + cj * b_qq.y;
                sA[pi * SROW + pj] = n_pp; sA[pi * SROW + qj] = n_pq;
                sA[qi * SROW + pj] = n_qp; sA[qi * SROW + qj] = n_qq;
            }
            // UT row mixing (independent of A update; same barrier region)
            for (int t = tid; t < 64 * NN; t += 1024) {
                int m = t >> 7, i = t & 127;
                if (striv[m]) continue;
                int p = sp[m], q = sq[m];
                float c = scc[m], zr = ssr[m], zi = ssi[m];
                float2 vp = UT[p * NN + i], vq = UT[q * NN + i];
                float2 np, nq;
                np.x = c * vp.x - (zr * vq.x + zi * vq.y);
                np.y = c * vp.y - (zr * vq.y - zi * vq.x);
                nq.x = (zr * vp.x - zi * vp.y) + c * vq.x;
                nq.y = (zr * vp.y + zi * vp.x) + c * vq.y;
                UT[p * NN + i] = np; UT[q * NN + i] = nq;
            }
            __syncthreads();
        }
    }
    if (tid < NN) g_w[b * NN + tid] = (double)sA[tid * SROW + tid].x;
}

// ------- rank eigenvalues ascending, shift by minv[rank], clip at 0 ---------
__global__ void rank_clip_kernel(int it) {
    int b = blockIdx.x, j = threadIdx.x;   // 128 threads
    __shared__ double w[NN];
    w[j] = g_w[b * NN + j];
    __syncthreads();
    double wj = w[j];
    int rank = 0;
    for (int k = 0; k < NN; ++k) {
        double wk = w[k];
        rank += (wk < wj) || (wk == wj && k < j);
    }
    double d = wj + g_minv[((size_t)it * NB + b) * NN + rank];
    g_sdf[b * NN + j] = (float)(d > 0.0 ? d : 0.0);
}

// ---- fp32 Sita = V diag(d) V^H  -> g_P scratch ------------------------------
__global__ __launch_bounds__(256) void sita_gemm_kernel(const float2* __restrict__ VTall) {
    int bid = blockIdx.x;
    int b  = bid >> 4;
    int ti = (bid >> 2) & 3, tj = bid & 3;
    size_t base = (size_t)b * NN * NN;
    const float2* __restrict__ VT = VTall + base;

    __shared__ float2 As[32][33];
    __shared__ float2 Bs[32][33];
    int tx = threadIdx.x & 15, ty = threadIdx.x >> 4;
    int i0 = ti * 32, j0 = tj * 32;
    float2 acc[2][2];
    acc[0][0] = acc[0][1] = acc[1][0] = acc[1][1] = make_float2(0.0f, 0.0f);

    for (int k0 = 0; k0 < NN; k0 += 32) {
        for (int l = threadIdx.x; l < 32 * 32; l += 256) {
            int rr = l & 31, kk = l >> 5;
            float dk = g_sdf[b * NN + k0 + kk];
            float2 v = VT[(size_t)(k0 + kk) * NN + i0 + rr];
            As[rr][kk] = make_float2(v.x * dk, v.y * dk);
            Bs[rr][kk] = VT[(size_t)(k0 + kk) * NN + j0 + rr];
        }
        __syncthreads();
#pragma unroll 8
        for (int kk = 0; kk < 32; ++kk) {
            float2 a0 = As[ty][kk],      a1 = As[ty + 16][kk];
            float2 b0 = Bs[tx][kk],      b1 = Bs[tx + 16][kk];
            acc[0][0].x += a0.x * b0.x + a0.y * b0.y; acc[0][0].y += a0.y * b0.x - a0.x * b0.y;
            acc[0][1].x += a0.x * b1.x + a0.y * b1.y; acc[0][1].y += a0.y * b1.x - a0.x * b1.y;
            acc[1][0].x += a1.x * b0.x + a1.y * b0.y; acc[1][0].y += a1.y * b0.x - a1.x * b0.y;
            acc[1][1].x += a1.x * b1.x + a1.y * b1.y; acc[1][1].y += a1.y * b1.x - a1.x * b1.y;
        }
        __syncthreads();
    }
    for (int r2 = 0; r2 < 2; ++r2)
        for (int c2 = 0; c2 < 2; ++c2)
            g_P[base + (size_t)(i0 + ty + 16 * r2) * NN + j0 + tx + 16 * c2] = acc[r2][c2];
}

// ---- Hermitize Sita (like reference); Theta = H; Lamda += e*(H - StackM) ---
__global__ __launch_bounds__(1024) void herm_update_kernel(const float* __restrict__ eta, int it) {
    int b = blockIdx.x, tid = threadIdx.x;
    double e = (double)eta[it];
    size_t base = (size_t)b * NN * NN;
    for (int idx = tid; idx < NN * NN; idx += 1024) {
        int i = idx >> 7, j = idx & 127;
        float2 sij = g_P[base + idx];
        float2 sji = g_P[base + (size_t)j * NN + i];
        double hx = 0.5 * ((double)sij.x + (double)sji.x);
        double hy = 0.5 * ((double)sij.y - (double)sji.y);
        g_Theta[base + idx] = make_double2(hx, hy);
        double2 L = g_Lamda[base + idx];
        double2 S = g_S[base + idx];
        L.x += e * (hx - S.x);
        L.y += e * (hy - S.y);
        g_Lamda[base + idx] = L;
    }
}

// ---------------- output writers (dtype-adaptive) ---------------------------
__global__ void output_f32i_kernel(float* __restrict__ out, int out_elems) {
    int b = blockIdx.x, tid = threadIdx.x;   // 256
    const double2* T = g_T + (size_t)b * MM * MM;
    for (int idx = tid; idx < MM * MM; idx += 256) {
        double2 v = T[idx];
        size_t o = ((size_t)b * MM * MM + idx) * 2;
        if (o + 1 < (size_t)out_elems) {
            out[o]     = (float)v.x;
            out[o + 1] = (float)v.y;
        }
    }
    if (tid < MM) {
        int k = tid;
        double ax = 0.0, ay = 0.0;
        for (int i = k; i < MM; ++i) {
            double2 v = T[(size_t)i * MM + (i - k)];
            ax += v.x; ay += v.y;
        }
        double nk = 1.0 / (double)(MM - k);
        size_t o = 2 * (size_t)NB * MM * MM + ((size_t)b * MM + k) * 2;
        if (o + 1 < (size_t)out_elems) {
            out[o]     = (float)(ax * nk);
            out[o + 1] = (float)(ay * nk);
        }
    }
}

__global__ void output_f32r_kernel(float* __restrict__ out, int out_elems) {
    int b = blockIdx.x, tid = threadIdx.x;   // 256
    const double2* T = g_T + (size_t)b * MM * MM;
    for (int idx = tid; idx < MM * MM; idx += 256) {
        size_t o = (size_t)b * MM * MM + idx;
        if (o < (size_t)out_elems) out[o] = (float)T[idx].x;
    }
    if (tid < MM) {
        int k = tid;
        double ax = 0.0;
        for (int i = k; i < MM; ++i) ax += T[(size_t)i * MM + (i - k)].x;
        size_t o = (size_t)NB * MM * MM + (size_t)b * MM + k;
        if (o < (size_t)out_elems) out[o] = (float)(ax / (double)(MM - k));
    }
}

extern "C" void kernel_launch(void* const* d_in, const int* in_sizes, int n_in,
                              void* d_out, int out_size) {
    const float* Yr  = (const float*)d_in[0];
    const float* Yi  = (const float*)d_in[1];
    const float* rho = (const float*)d_in[2];
    const float* tau = (const float*)d_in[3];
    const float* eta = (const float*)d_in[4];

    static bool s_init = false;
    static float2 *s_Af, *s_P, *s_Bf, *s_Uf, *s_VT0;
    if (!s_init) {
        const int JSMEM0 = NN * SROW * (int)sizeof(float2);  // 132096 B
        cudaFuncSetAttribute(jacobi_kernel,
                             cudaFuncAttributeMaxDynamicSharedMemorySize, JSMEM0);
        void* p;
        cudaGetSymbolAddress(&p, g_Af);  s_Af  = (float2*)p;
        cudaGetSymbolAddress(&p, g_P);   s_P   = (float2*)p;
        cudaGetSymbolAddress(&p, g_Bf);  s_Bf  = (float2*)p;
        cudaGetSymbolAddress(&p, g_Uf);  s_Uf  = (float2*)p;
        cudaGetSymbolAddress(&p, g_VT);  s_VT0 = (float2*)p;
        s_init = true;
    }
    const int JSMEM = NN * SROW * (int)sizeof(float2);
    const size_t VTSZ = (size_t)NB * NN * NN;

    zero_kernel<<<(NB * NN * NN + 255) / 256, 256>>>();
    minv_kernel<<<(KIT * NB * NN + 255) / 256, 256>>>();

    for (int it = 0; it < KIT; ++it) {
        float2* VTsrc = s_VT0 + (size_t)(it & 1) * VTSZ;
        float2* VTdst = s_VT0 + (size_t)((it + 1) & 1) * VTSZ;

        prepare_kernel<<<NB, 256>>>(Yr, Yi, rho, tau, it);
        // warm start: B = V_prev^H A V_prev
        gemm_nt_kernel<<<NB * 16, 256>>>(s_Af, VTsrc, s_P);           // P = A * VT^T
        gemm_nn_kernel<true><<<NB * 16, 256>>>(VTsrc, s_P, s_Bf);     // B = conj(VT) * P
        jacobi_kernel<<<NB, 1024, JSMEM>>>();
        rank_clip_kernel<<<NB, NN>>>(it);
        gemm_nn_kernel<false><<<NB * 16, 256>>>(s_Uf, VTsrc, VTdst);  // VT_new = UT * VT_prev
        sita_gemm_kernel<<<NB * 16, 256>>>(VTdst);                    // fp32 Sita -> g_P
        herm_update_kernel<<<NB, 1024>>>(eta, it);                    // Hermitize + Theta/Lamda
    }

    const long long total_c = (long long)NB * MM * MM + (long long)NB * MM; // 266240
    if ((long long)out_size >= 2 * total_c) {
        output_f32i_kernel<<<NB, 256>>>((float*)d_out, out_size);
    } else {
        output_f32r_kernel<<<NB, 256>>>((float*)d_out, out_size);
    }
}

// round 16
// speedup vs baseline: 34.3066x; 1.0309x over previous
#include <cuda_runtime.h>
#include <math.h>

#define NB 64
#define MM 64
#define NN 128
#define KIT 10
#define SROW 129   // padded smem row stride (float2)

// ---------------- persistent device state ----------------------------------
__device__ double2 g_Theta[NB * NN * NN];   // fp64 ADMM state
__device__ double2 g_Lamda[NB * NN * NN];
__device__ double2 g_S[NB * NN * NN];       // StackM (fp64)
__device__ double2 g_T[NB * MM * MM];
__device__ float2  g_Af[NB * NN * NN];      // fp32 A; later NS scratch H
__device__ float2  g_P [NB * NN * NN];      // scratch: warm-start P / raw VT / fp32 Sita
__device__ float2  g_Bf[NB * NN * NN];      // jacobi input: B = V^H A V
__device__ float2  g_Uf[NB * NN * NN];      // jacobi output UT (U transposed)
__device__ float2  g_VT[2][NB * NN * NN];   // accumulated eigvecs, transposed, dbl-buffered
__device__ double  g_minv[KIT * NB * NN];
__device__ double  g_w[NB * NN];
__device__ float   g_sdf[NB * NN];

// ---------------- threefry2x32 (JAX-compatible) ----------------------------
__device__ __forceinline__ void tf2x32(unsigned k0, unsigned k1,
                                       unsigned &x0, unsigned &x1) {
    unsigned ks2 = k0 ^ k1 ^ 0x1BD11BDAu;
    x0 += k0; x1 += k1;
#define TF_ROT(x, d) (((x) << (d)) | ((x) >> (32 - (d))))
#define TF_RND(r) do { x0 += x1; x1 = TF_ROT(x1, r); x1 ^= x0; } while (0)
    TF_RND(13); TF_RND(15); TF_RND(26); TF_RND(6);
    x0 += k1;  x1 += ks2 + 1u;
    TF_RND(17); TF_RND(29); TF_RND(16); TF_RND(24);
    x0 += ks2; x1 += k0 + 2u;
    TF_RND(13); TF_RND(15); TF_RND(26); TF_RND(6);
    x0 += k0;  x1 += k1 + 3u;
    TF_RND(17); TF_RND(29); TF_RND(16); TF_RND(24);
    x0 += k1;  x1 += ks2 + 4u;
    TF_RND(13); TF_RND(15); TF_RND(26); TF_RND(6);
    x0 += ks2; x1 += k0 + 5u;
#undef TF_RND
#undef TF_ROT
}

__global__ void minv_kernel() {
    int idx = blockIdx.x * blockDim.x + threadIdx.x;
    if (idx >= KIT * NB * NN) return;
    int it = idx / (NB * NN);
    unsigned i = (unsigned)(idx % (NB * NN));
    unsigned k0 = 0u, k1 = (unsigned)it;
    tf2x32(0u, 42u, k0, k1);
    unsigned y0 = 0u, y1 = i;
    tf2x32(k0, k1, y0, y1);
    unsigned long long bits = ((unsigned long long)y0 << 32) | (unsigned long long)y1;
    unsigned long long fb = (bits >> 12) | 0x3FF0000000000000ULL;
    double f  = __longlong_as_double((long long)fb) - 1.0;
    double lo = __longlong_as_double((long long)0xBFEFFFFFFFFFFFFFULL);
    double u  = f * 2.0 + lo;
    u = fmax(lo, u);
    g_minv[idx] = 1.4142135623730951 * erfinv(u);
}

__global__ void zero_kernel() {
    int idx = blockIdx.x * blockDim.x + threadIdx.x;
    if (idx < NB * NN * NN) {
        g_Theta[idx] = make_double2(0.0, 0.0);
        g_Lamda[idx] = make_double2(0.0, 0.0);
        int i = (idx >> 7) & 127, j = idx & 127;
        g_VT[0][idx] = make_float2((i == j) ? 1.0f : 0.0f, 0.0f);
    }
}

// --------- per-iteration: StackM (g_S), T block, A_f32 = StackM - Lamda/r ---
__global__ void prepare_kernel(const float* __restrict__ Yr,
                               const float* __restrict__ Yi,
                               const float* __restrict__ rho,
                               const float* __restrict__ tau, int it) {
    int b = blockIdx.x;
    int tid = threadIdx.x;              // 256
    double r = (double)rho[it];
    double t = (double)tau[it];
    size_t base = (size_t)b * NN * NN;

    __shared__ double2 su[MM];
    if (tid < MM) {
        int k = tid;
        double ax = 0.0, ay = 0.0;
        for (int i = 0; i + k < MM; ++i) {
            double2 L  = g_Lamda[base + (size_t)i * NN + i + k];
            double2 Th = g_Theta[base + (size_t)i * NN + i + k];
            ax += L.x + r * Th.x;
            ay += L.y + r * Th.y;
        }
        if (k == 0) ax += -(t * 0.5) * (double)MM;
        double sc = (1.0 / (double)(MM - k)) / r;
        su[k] = make_double2(ax * sc, ay * sc);
    }
    __syncthreads();

    double inv1 = 1.0 / (1.0 + 2.0 * r);
    double invr = 1.0 / r;
    double tdr  = t / (2.0 * r);
    for (int idx = tid; idx < NN * NN; idx += blockDim.x) {
        int i = idx >> 7, j = idx & 127;
        double2 S;
        if (i < MM && j < MM) {
            S = (j >= i) ? su[j - i] : make_double2(su[i - j].x, -su[i - j].y);
            g_T[(size_t)b * MM * MM + i * MM + j] = S;
        } else if (i < MM) {
            int jj = j - MM;
            double2 L = g_Lamda[base + idx], Th = g_Theta[base + idx];
            double yr = (double)Yr[(size_t)b * MM * MM + i * MM + jj];
            double yi = (double)Yi[(size_t)b * MM * MM + i * MM + jj];
            S.x = (yr + 2.0 * L.x + 2.0 * r * Th.x) * inv1;
            S.y = (yi + 2.0 * L.y + 2.0 * r * Th.y) * inv1;
        } else if (j < MM) {
            int ii = j, jj = i - MM;
            size_t xo = base + (size_t)ii * NN + MM + jj;
            double2 L = g_Lamda[xo], Th = g_Theta[xo];
            double yr = (double)Yr[(size_t)b * MM * MM + ii * MM + jj];
            double yi = (double)Yi[(size_t)b * MM * MM + ii * MM + jj];
            S.x =  (yr + 2.0 * L.x + 2.0 * r * Th.x) * inv1;
            S.y = -((yi + 2.0 * L.y + 2.0 * r * Th.y) * inv1);
        } else {
            double2 L = g_Lamda[base + idx], Th = g_Theta[base + idx];
            S.x = L.x * invr + Th.x - ((i == j) ? tdr : 0.0);
            S.y = L.y * invr + Th.y;
        }
        g_S[base + idx] = S;
        double2 L = g_Lamda[base + idx];
        g_Af[base + idx] = make_float2((float)(S.x - L.x * invr),
                                       (float)(S.y - L.y * invr));
    }
}

// ---------------- tiled complex gemms (per-batch 128x128) -------------------
// NT: C[i][l] = sum_j A[i][j] * opB(Bt[l][j])   (opB = conj if CONJB)
template <bool CONJB>
__global__ __launch_bounds__(256) void gemm_nt_kernel(const float2* __restrict__ A,
                                                      const float2* __restrict__ Bt,
                                                      float2* __restrict__ C) {
    int bid = blockIdx.x;
    int b  = bid >> 4;
    int ti = (bid >> 2) & 3, tj = bid & 3;
    size_t base = (size_t)b * NN * NN;
    __shared__ float2 As[32][33];
    __shared__ float2 Bs[32][33];
    int tx = threadIdx.x & 15, ty = threadIdx.x >> 4;
    int i0 = ti * 32, j0 = tj * 32;
    float2 acc[2][2];
    acc[0][0] = acc[0][1] = acc[1][0] = acc[1][1] = make_float2(0.f, 0.f);
    for (int k0 = 0; k0 < NN; k0 += 32) {
        for (int l = threadIdx.x; l < 32 * 32; l += 256) {
            int rr = l >> 5, kk = l & 31;
            As[rr][kk] = A [base + (size_t)(i0 + rr) * NN + k0 + kk];
            float2 bv = Bt[base + (size_t)(j0 + rr) * NN + k0 + kk];
            if (CONJB) bv.y = -bv.y;
            Bs[rr][kk] = bv;
        }
        __syncthreads();
#pragma unroll 8
        for (int kk = 0; kk < 32; ++kk) {
            float2 a0 = As[ty][kk], a1 = As[ty + 16][kk];
            float2 b0 = Bs[tx][kk], b1 = Bs[tx + 16][kk];
            acc[0][0].x += a0.x * b0.x - a0.y * b0.y; acc[0][0].y += a0.x * b0.y + a0.y * b0.x;
            acc[0][1].x += a0.x * b1.x - a0.y * b1.y; acc[0][1].y += a0.x * b1.y + a0.y * b1.x;
            acc[1][0].x += a1.x * b0.x - a1.y * b0.y; acc[1][0].y += a1.x * b0.y + a1.y * b0.x;
            acc[1][1].x += a1.x * b1.x - a1.y * b1.y; acc[1][1].y += a1.x * b1.y + a1.y * b1.x;
        }
        __syncthreads();
    }
    for (int r2 = 0; r2 < 2; ++r2)
        for (int c2 = 0; c2 < 2; ++c2)
            C[base + (size_t)(i0 + ty + 16 * r2) * NN + j0 + tx + 16 * c2] = acc[r2][c2];
}

// NN: C[k][l] = sum_i opA(A[k][i]) * B[i][l]   (opA = conj if CONJA)
template <bool CONJA>
__global__ __launch_bounds__(256) void gemm_nn_kernel(const float2* __restrict__ A,
                                                      const float2* __restrict__ B,
                                                      float2* __restrict__ C) {
    int bid = blockIdx.x;
    int b  = bid >> 4;
    int ti = (bid >> 2) & 3, tj = bid & 3;
    size_t base = (size_t)b * NN * NN;
    __shared__ float2 As[32][33];
    __shared__ float2 Bs[32][33];
    int tx = threadIdx.x & 15, ty = threadIdx.x >> 4;
    int i0 = ti * 32, j0 = tj * 32;
    float2 acc[2][2];
    acc[0][0] = acc[0][1] = acc[1][0] = acc[1][1] = make_float2(0.f, 0.f);
    for (int k0 = 0; k0 < NN; k0 += 32) {
        for (int l = threadIdx.x; l < 32 * 32; l += 256) {
            int rr = l >> 5, kk = l & 31;
            As[rr][kk] = A[base + (size_t)(i0 + rr) * NN + k0 + kk];
            Bs[rr][kk] = B[base + (size_t)(k0 + rr) * NN + j0 + kk];
        }
        __syncthreads();
#pragma unroll 8
        for (int kk = 0; kk < 32; ++kk) {
            float2 a0 = As[ty][kk], a1 = As[ty + 16][kk];
            float2 b0 = Bs[kk][tx], b1 = Bs[kk][tx + 16];
            if (CONJA) {
                acc[0][0].x += a0.x * b0.x + a0.y * b0.y; acc[0][0].y += a0.x * b0.y - a0.y * b0.x;
                acc[0][1].x += a0.x * b1.x + a0.y * b1.y; acc[0][1].y += a0.x * b1.y - a0.y * b1.x;
                acc[1][0].x += a1.x * b0.x + a1.y * b0.y; acc[1][0].y += a1.x * b0.y - a1.y * b0.x;
                acc[1][1].x += a1.x * b1.x + a1.y * b1.y; acc[1][1].y += a1.x * b1.y - a1.y * b1.x;
            } else {
                acc[0][0].x += a0.x * b0.x - a0.y * b0.y; acc[0][0].y += a0.x * b0.y + a0.y * b0.x;
                acc[0][1].x += a0.x * b1.x - a0.y * b1.y; acc[0][1].y += a0.x * b1.y + a0.y * b1.x;
                acc[1][0].x += a1.x * b0.x - a1.y * b0.y; acc[1][0].y += a1.x * b0.y + a1.y * b0.x;
                acc[1][1].x += a1.x * b1.x - a1.y * b1.y; acc[1][1].y += a1.x * b1.y + a1.y * b1.x;
            }
        }
        __syncthreads();
    }
    for (int r2 = 0; r2 < 2; ++r2)
        for (int c2 = 0; c2 < 2; ++c2)
            C[base + (size_t)(i0 + ty + 16 * r2) * NN + j0 + tx + 16 * c2] = acc[r2][c2];
}

// Newton-Schulz combine: C = 1.5*B - 0.5*(H @ B)    (H ~ I, Hermitian)
__global__ __launch_bounds__(256) void gemm_ns_kernel(const float2* __restrict__ H,
                                                      const float2* __restrict__ B,
                                                      float2* __restrict__ C) {
    int bid = blockIdx.x;
    int b  = bid >> 4;
    int ti = (bid >> 2) & 3, tj = bid & 3;
    size_t base = (size_t)b * NN * NN;
    __shared__ float2 As[32][33];
    __shared__ float2 Bs[32][33];
    int tx = threadIdx.x & 15, ty = threadIdx.x >> 4;
    int i0 = ti * 32, j0 = tj * 32;
    float2 acc[2][2];
    acc[0][0] = acc[0][1] = acc[1][0] = acc[1][1] = make_float2(0.f, 0.f);
    for (int k0 = 0; k0 < NN; k0 += 32) {
        for (int l = threadIdx.x; l < 32 * 32; l += 256) {
            int rr = l >> 5, kk = l & 31;
            As[rr][kk] = H[base + (size_t)(i0 + rr) * NN + k0 + kk];
            Bs[rr][kk] = B[base + (size_t)(k0 + rr) * NN + j0 + kk];
        }
        __syncthreads();
#pragma unroll 8
        for (int kk = 0; kk < 32; ++kk) {
            float2 a0 = As[ty][kk], a1 = As[ty + 16][kk];
            float2 b0 = Bs[kk][tx], b1 = Bs[kk][tx + 16];
            acc[0][0].x += a0.x * b0.x - a0.y * b0.y; acc[0][0].y += a0.x * b0.y + a0.y * b0.x;
            acc[0][1].x += a0.x * b1.x - a0.y * b1.y; acc[0][1].y += a0.x * b1.y + a0.y * b1.x;
            acc[1][0].x += a1.x * b0.x - a1.y * b0.y; acc[1][0].y += a1.x * b0.y + a1.y * b0.x;
            acc[1][1].x += a1.x * b1.x - a1.y * b1.y; acc[1][1].y += a1.x * b1.y + a1.y * b1.x;
        }
        __syncthreads();
    }
    for (int r2 = 0; r2 < 2; ++r2)
        for (int c2 = 0; c2 < 2; ++c2) {
            size_t idx = base + (size_t)(i0 + ty + 16 * r2) * NN + j0 + tx + 16 * c2;
            float2 bv = B[idx];
            float2 av = acc[r2][c2];
            C[idx] = make_float2(1.5f * bv.x - 0.5f * av.x,
                                 1.5f * bv.y - 0.5f * av.y);
        }
}

// ---------------- fp32 parallel Hermitian Jacobi, fused 2x2-block update ----
__device__ __forceinline__ double block_reduce(double v, double* sred, int tid) {
    for (int o = 16; o; o >>= 1) v += __shfl_down_sync(0xffffffffu, v, o);
    if ((tid & 31) == 0) sred[tid >> 5] = v;
    __syncthreads();
    if (tid < 32) {
        double x = sred[tid];
        for (int o = 16; o; o >>= 1) x += __shfl_down_sync(0xffffffffu, x, o);
        if (tid == 0) sred[0] = x;
    }
    __syncthreads();
    double r = sred[0];
    __syncthreads();
    return r;
}

__global__ __launch_bounds__(1024, 1) void jacobi_kernel() {
    extern __shared__ float2 sA[];   // [128][SROW]
    int b = blockIdx.x, tid = threadIdx.x;
    const float2* __restrict__ Bg = g_Bf + (size_t)b * NN * NN;
    float2* __restrict__ UT = g_Uf + (size_t)b * NN * NN;

    __shared__ int   sp[64], sq[64], striv[64];
    __shared__ float scc[64], ssr[64], ssi[64];
    __shared__ double sred[32];

    // load with Hermitization: sA = (B + B^H)/2
    for (int idx = tid; idx < NN * NN; idx += 1024) {
        int i = idx >> 7, j = idx & 127;
        float2 bij = Bg[idx];
        float2 bji = Bg[(size_t)j * NN + i];
        sA[i * SROW + j] = make_float2(0.5f * (bij.x + bji.x),
                                       0.5f * (bij.y - bji.y));
        UT[idx] = make_float2(i == j ? 1.0f : 0.0f, 0.0f);
    }
    __syncthreads();

    double acc = 0.0;
    for (int idx = tid; idx < NN * NN; idx += 1024) {
        int i = idx >> 7, j = idx & 127;
        float2 a = sA[i * SROW + j];
        acc += (double)a.x * a.x + (double)a.y * a.y;
    }
    double tol2 = block_reduce(acc, sred, tid) * 1e-11;
    float sthr = (float)(tol2 * (1.0 / 8192.0));   // per-pair skip threshold

    double prev = 1e300;
    for (int sweep = 0; sweep < 16; ++sweep) {
        acc = 0.0;
        for (int idx = tid; idx < NN * NN; idx += 1024) {
            int i = idx >> 7, j = idx & 127;
            if (i != j) {
                float2 a = sA[i * SROW + j];
                acc += (double)a.x * a.x + (double)a.y * a.y;
            }
        }
        double off2 = block_reduce(acc, sred, tid);
        // exit on convergence OR stagnation at the fp32 noise floor
        if (off2 <= tol2 || off2 > 0.7 * prev) break;
        prev = off2;

        for (int r = 0; r < NN - 1; ++r) {
            if (tid < 64) {
                int p, q;
                if (tid == 0) { p = NN - 1; q = r % (NN - 1); }
                else {
                    p = (r + tid) % (NN - 1);
                    q = (r - tid + 2 * (NN - 1)) % (NN - 1);
                }
                sp[tid] = p; sq[tid] = q;
                float app = sA[p * SROW + p].x;
                float aqq = sA[q * SROW + q].x;
                float2 apq = sA[p * SROW + q];
                float mag2 = apq.x * apq.x + apq.y * apq.y;
                float c = 1.0f, zr = 0.0f, zi = 0.0f;
                int trivial = 1;
                if (mag2 > sthr && mag2 > 1e-28f) {
                    trivial = 0;
                    float mag = sqrtf(mag2);
                    float th  = (aqq - app) / (2.0f * mag);
                    float rt  = sqrtf(th * th + 1.0f);
                    float tt  = (th >= 0.0f) ? 1.0f / (th + rt) : -1.0f / (rt - th);
                    c = rsqrtf(1.0f + tt * tt);
                    float sg = tt * c / mag;
                    zr = sg * apq.x; zi = sg * apq.y;
                }
                scc[tid] = c; ssr[tid] = zr; ssi[tid] = zi; striv[tid] = trivial;
            }
            __syncthreads();

            // fused update: A' = R^H A R on disjoint 2x2 blocks (mi, mj)
            for (int t = tid; t < 64 * 64; t += 1024) {
                int mi = t >> 6, mj = t & 63;
                if (striv[mi] && striv[mj]) continue;
                int pi = sp[mi], qi = sq[mi], pj = sp[mj], qj = sq[mj];
                float ci = scc[mi], zri = ssr[mi], zii = ssi[mi];
                float cj = scc[mj], zrj = ssr[mj], zij = ssi[mj];
                float2 app = sA[pi * SROW + pj], apq = sA[pi * SROW + qj];
                float2 aqp = sA[qi * SROW + pj], aqq = sA[qi * SROW + qj];
                float2 b_pp, b_qp, b_pq, b_qq;
                b_pp.x = ci * app.x - (zri * aqp.x - zii * aqp.y);
                b_pp.y = ci * app.y - (zri * aqp.y + zii * aqp.x);
                b_qp.x = (zri * app.x + zii * app.y) + ci * aqp.x;
                b_qp.y = (zri * app.y - zii * app.x) + ci * aqp.y;
                b_pq.x = ci * apq.x - (zri * aqq.x - zii * aqq.y);
                b_pq.y = ci * apq.y - (zri * aqq.y + zii * aqq.x);
                b_qq.x = (zri * apq.x + zii * apq.y) + ci * aqq.x;
                b_qq.y = (zri * apq.y - zii * apq.x) + ci * aqq.y;
                float2 n_pp, n_pq, n_qp, n_qq;
                n_pp.x = cj * b_pp.x - (zrj * b_pq.x + zij * b_pq.y);
                n_pp.y = cj * b_pp.y - (zrj * b_pq.y - zij * b_pq.x);
                n_pq.x = (zrj * b_pp.x - zij * b_pp.y) + cj * b_pq.x;
                n_pq.y = (zrj * b_pp.y + zij * b_pp.x) + cj * b_pq.y;
                n_qp.x = cj * b_qp.x - (zrj * b_qq.x + zij * b_qq.y);
                n_qp.y = cj * b_qp.y - (zrj * b_qq.y - zij * b_qq.x);
                n_qq.x = (zrj * b_qp.x - zij * b_qp.y) + cj * b_qq.x;
                n_qq.y = (zrj * b_qp.y + zij * b_qp.x) + cj * b_qq.y;
                sA[pi * SROW + pj] = n_pp; sA[pi * SROW + qj] = n_pq;
                sA[qi * SROW + pj] = n_qp; sA[qi * SROW + qj] = n_qq;
            }
            // UT row mixing
            for (int t = tid; t < 64 * NN; t += 1024) {
                int m = t >> 7, i = t & 127;
                if (striv[m]) continue;
                int p = sp[m], q = sq[m];
                float c = scc[m], zr = ssr[m], zi = ssi[m];
                float2 vp = UT[p * NN + i], vq = UT[q * NN + i];
                float2 np, nq;
                np.x = c * vp.x - (zr * vq.x + zi * vq.y);
                np.y = c * vp.y - (zr * vq.y - zi * vq.x);
                nq.x = (zr * vp.x - zi * vp.y) + c * vq.x;
                nq.y = (zr * vp.y + zi * vp.x) + c * vq.y;
                UT[p * NN + i] = np; UT[q * NN + i] = nq;
            }
            __syncthreads();
        }
    }
    if (tid < NN) g_w[b * NN + tid] = (double)sA[tid * SROW + tid].x;
}

// ------- rank eigenvalues ascending, shift by minv[rank], clip at 0 ---------
__global__ void rank_clip_kernel(int it) {
    int b = blockIdx.x, j = threadIdx.x;   // 128 threads
    __shared__ double w[NN];
    w[j] = g_w[b * NN + j];
    __syncthreads();
    double wj = w[j];
    int rank = 0;
    for (int k = 0; k < NN; ++k) {
        double wk = w[k];
        rank += (wk < wj) || (wk == wj && k < j);
    }
    double d = wj + g_minv[((size_t)it * NB + b) * NN + rank];
    g_sdf[b * NN + j] = (float)(d > 0.0 ? d : 0.0);
}

// ---- fp32 Sita = V diag(d) V^H  -> g_P scratch ------------------------------
__global__ __launch_bounds__(256) void sita_gemm_kernel(const float2* __restrict__ VTall) {
    int bid = blockIdx.x;
    int b  = bid >> 4;
    int ti = (bid >> 2) & 3, tj = bid & 3;
    size_t base = (size_t)b * NN * NN;
    const float2* __restrict__ VT = VTall + base;

    __shared__ float2 As[32][33];
    __shared__ float2 Bs[32][33];
    int tx = threadIdx.x & 15, ty = threadIdx.x >> 4;
    int i0 = ti * 32, j0 = tj * 32;
    float2 acc[2][2];
    acc[0][0] = acc[0][1] = acc[1][0] = acc[1][1] = make_float2(0.0f, 0.0f);

    for (int k0 = 0; k0 < NN; k0 += 32) {
        for (int l = threadIdx.x; l < 32 * 32; l += 256) {
            int rr = l & 31, kk = l >> 5;
            float dk = g_sdf[b * NN + k0 + kk];
            float2 v = VT[(size_t)(k0 + kk) * NN + i0 + rr];
            As[rr][kk] = make_float2(v.x * dk, v.y * dk);
            Bs[rr][kk] = VT[(size_t)(k0 + kk) * NN + j0 + rr];
        }
        __syncthreads();
#pragma unroll 8
        for (int kk = 0; kk < 32; ++kk) {
            float2 a0 = As[ty][kk],      a1 = As[ty + 16][kk];
            float2 b0 = Bs[tx][kk],      b1 = Bs[tx + 16][kk];
            acc[0][0].x += a0.x * b0.x + a0.y * b0.y; acc[0][0].y += a0.y * b0.x - a0.x * b0.y;
            acc[0][1].x += a0.x * b1.x + a0.y * b1.y; acc[0][1].y += a0.y * b1.x - a0.x * b1.y;
            acc[1][0].x += a1.x * b0.x + a1.y * b0.y; acc[1][0].y += a1.y * b0.x - a1.x * b0.y;
            acc[1][1].x += a1.x * b1.x + a1.y * b1.y; acc[1][1].y += a1.y * b1.x - a1.x * b1.y;
        }
        __syncthreads();
    }
    for (int r2 = 0; r2 < 2; ++r2)
        for (int c2 = 0; c2 < 2; ++c2)
            g_P[base + (size_t)(i0 + ty + 16 * r2) * NN + j0 + tx + 16 * c2] = acc[r2][c2];
}

// ---- Hermitize Sita; Theta = H; Lamda += e*(H - StackM) --------------------
__global__ __launch_bounds__(1024) void herm_update_kernel(const float* __restrict__ eta, int it) {
    int b = blockIdx.x, tid = threadIdx.x;
    double e = (double)eta[it];
    size_t base = (size_t)b * NN * NN;
    for (int idx = tid; idx < NN * NN; idx += 1024) {
        int i = idx >> 7, j = idx & 127;
        float2 sij = g_P[base + idx];
        float2 sji = g_P[base + (size_t)j * NN + i];
        double hx = 0.5 * ((double)sij.x + (double)sji.x);
        double hy = 0.5 * ((double)sij.y - (double)sji.y);
        g_Theta[base + idx] = make_double2(hx, hy);
        double2 L = g_Lamda[base + idx];
        double2 S = g_S[base + idx];
        L.x += e * (hx - S.x);
        L.y += e * (hy - S.y);
        g_Lamda[base + idx] = L;
    }
}

// ---------------- output writers (dtype-adaptive) ---------------------------
__global__ void output_f32i_kernel(float* __restrict__ out, int out_elems) {
    int b = blockIdx.x, tid = threadIdx.x;   // 256
    const double2* T = g_T + (size_t)b * MM * MM;
    for (int idx = tid; idx < MM * MM; idx += 256) {
        double2 v = T[idx];
        size_t o = ((size_t)b * MM * MM + idx) * 2;
        if (o + 1 < (size_t)out_elems) {
            out[o]     = (float)v.x;
            out[o + 1] = (float)v.y;
        }
    }
    if (tid < MM) {
        int k = tid;
        double ax = 0.0, ay = 0.0;
        for (int i = k; i < MM; ++i) {
            double2 v = T[(size_t)i * MM + (i - k)];
            ax += v.x; ay += v.y;
        }
        double nk = 1.0 / (double)(MM - k);
        size_t o = 2 * (size_t)NB * MM * MM + ((size_t)b * MM + k) * 2;
        if (o + 1 < (size_t)out_elems) {
            out[o]     = (float)(ax * nk);
            out[o + 1] = (float)(ay * nk);
        }
    }
}

__global__ void output_f32r_kernel(float* __restrict__ out, int out_elems) {
    int b = blockIdx.x, tid = threadIdx.x;   // 256
    const double2* T = g_T + (size_t)b * MM * MM;
    for (int idx = tid; idx < MM * MM; idx += 256) {
        size_t o = (size_t)b * MM * MM + idx;
        if (o < (size_t)out_elems) out[o] = (float)T[idx].x;
    }
    if (tid < MM) {
        int k = tid;
        double ax = 0.0;
        for (int i = k; i < MM; ++i) ax += T[(size_t)i * MM + (i - k)].x;
        size_t o = (size_t)NB * MM * MM + (size_t)b * MM + k;
        if (o < (size_t)out_elems) out[o] = (float)(ax / (double)(MM - k));
    }
}

extern "C" void kernel_launch(void* const* d_in, const int* in_sizes, int n_in,
                              void* d_out, int out_size) {
    const float* Yr  = (const float*)d_in[0];
    const float* Yi  = (const float*)d_in[1];
    const float* rho = (const float*)d_in[2];
    const float* tau = (const float*)d_in[3];
    const float* eta = (const float*)d_in[4];

    static bool s_init = false;
    static float2 *s_Af, *s_P, *s_Bf, *s_Uf, *s_VT0;
    if (!s_init) {
        const int JSMEM0 = NN * SROW * (int)sizeof(float2);  // 132096 B
        cudaFuncSetAttribute(jacobi_kernel,
                             cudaFuncAttributeMaxDynamicSharedMemorySize, JSMEM0);
        void* p;
        cudaGetSymbolAddress(&p, g_Af);  s_Af  = (float2*)p;
        cudaGetSymbolAddress(&p, g_P);   s_P   = (float2*)p;
        cudaGetSymbolAddress(&p, g_Bf);  s_Bf  = (float2*)p;
        cudaGetSymbolAddress(&p, g_Uf);  s_Uf  = (float2*)p;
        cudaGetSymbolAddress(&p, g_VT);  s_VT0 = (float2*)p;
        s_init = true;
    }
    const int JSMEM = NN * SROW * (int)sizeof(float2);
    const size_t VTSZ = (size_t)NB * NN * NN;

    zero_kernel<<<(NB * NN * NN + 255) / 256, 256>>>();
    minv_kernel<<<(KIT * NB * NN + 255) / 256, 256>>>();

    for (int it = 0; it < KIT; ++it) {
        float2* VTsrc = s_VT0 + (size_t)(it & 1) * VTSZ;
        float2* VTdst = s_VT0 + (size_t)((it + 1) & 1) * VTSZ;

        prepare_kernel<<<NB, 256>>>(Yr, Yi, rho, tau, it);
        // warm start: B = V_prev^H A V_prev
        gemm_nt_kernel<false><<<NB * 16, 256>>>(s_Af, VTsrc, s_P);    // P = A * VT^T
        gemm_nn_kernel<true><<<NB * 16, 256>>>(VTsrc, s_P, s_Bf);     // B = conj(VT) * P
        jacobi_kernel<<<NB, 1024, JSMEM>>>();
        rank_clip_kernel<<<NB, NN>>>(it);
        // VT accumulate + Newton-Schulz re-unitarization
        gemm_nn_kernel<false><<<NB * 16, 256>>>(s_Uf, VTsrc, s_P);    // raw VT_new -> P
        gemm_nt_kernel<true><<<NB * 16, 256>>>(s_P, s_P, s_Af);       // H = P * conj(P)^T
        gemm_ns_kernel<<<NB * 16, 256>>>(s_Af, s_P, VTdst);           // VTdst = 1.5P - 0.5HP
        sita_gemm_kernel<<<NB * 16, 256>>>(VTdst);                    // fp32 Sita -> g_P
        herm_update_kernel<<<NB, 1024>>>(eta, it);                    // Hermitize + Theta/Lamda
    }

    const long long total_c = (long long)NB * MM * MM + (long long)NB * MM; // 266240
    if ((long long)out_size >= 2 * total_c) {
        output_f32i_kernel<<<NB, 256>>>((float*)d_out, out_size);
    } else {
        output_f32r_kernel<<<NB, 256>>>((float*)d_out, out_size);
    }
}